// round 12
// baseline (speedup 1.0000x reference)
#include <cuda_runtime.h>
#include <cuda_bf16.h>
#include <cstdint>

#define DEVFN __device__ __forceinline__

constexpr int TOKENS = 16 * 56 * 56;   // 50176
constexpr float SCALE = 0.17677669529663687f;   // 32^-0.5

// Scratch (static device arrays: allocation-free per harness rules)
__device__ float g_q   [TOKENS * 256];
__device__ float g_k   [TOKENS * 256];
__device__ float g_v   [TOKENS * 256];
__device__ float g_x2  [TOKENS * 256];
__device__ float g_btile[512 * 49 * 56];            // fused rel_bias+mask
__device__ __nv_bfloat16 g_hw_bf [TOKENS * 256];    // LN1 out (windowed)
__device__ __nv_bfloat16 g_o_bf  [TOKENS * 256];    // attention out
__device__ __nv_bfloat16 g_h2n_bf[TOKENS * 256];    // LN2 out
__device__ __nv_bfloat16 g_mlp_bf[TOKENS * 1024];   // fc1+gelu out
__device__ __nv_bfloat16 g_wqkv_bf[768 * 256];
__device__ __nv_bfloat16 g_wprj_bf[256 * 256];
__device__ __nv_bfloat16 g_wfc1_bf[1024 * 256];
__device__ __nv_bfloat16 g_wfc2_bf[256 * 1024];

// ------------------------------ PTX helpers ---------------------------------
DEVFN uint32_t smem_u32(const void* p) {
    uint32_t a;
    asm("{ .reg .u64 t; cvta.to.shared.u64 t, %1; cvt.u32.u64 %0, t; }"
        : "=r"(a) : "l"(p));
    return a;
}
DEVFN uint32_t swz(uint32_t o) { return o ^ ((o >> 3) & 0x70u); }
DEVFN void cp16(uint32_t dst, const void* src) {
    asm volatile("cp.async.cg.shared.global [%0], [%1], 16;" :: "r"(dst), "l"(src));
}
DEVFN void cp_commit() { asm volatile("cp.async.commit_group;" ::: "memory"); }
template <int N> DEVFN void cp_wait() {
    asm volatile("cp.async.wait_group %0;" :: "n"(N) : "memory");
}
DEVFN float to_tf32(float x) {
    float r;
    asm("cvt.rna.tf32.f32 %0, %1;" : "=f"(r) : "f"(x));
    return r;
}
DEVFN uint32_t bfp(float a, float b) {   // pack 2 floats -> bf16x2 (RNE)
    __nv_bfloat162 t = __floats2bfloat162_rn(a, b);
    return *(uint32_t*)&t;
}
// tf32 mma (attention)
DEVFN void mma8(float c[4], const uint32_t a[4], const uint32_t b[2]) {
    asm volatile(
        "mma.sync.aligned.m16n8k8.row.col.f32.tf32.tf32.f32 "
        "{%0,%1,%2,%3}, {%4,%5,%6,%7}, {%8,%9}, {%0,%1,%2,%3};"
        : "+f"(c[0]), "+f"(c[1]), "+f"(c[2]), "+f"(c[3])
        : "r"(a[0]), "r"(a[1]), "r"(a[2]), "r"(a[3]), "r"(b[0]), "r"(b[1]));
}
// bf16 mma (GEMMs): K=16 per instruction
DEVFN void mma16(float c[4], const uint32_t a[4], const uint32_t b0, const uint32_t b1) {
    asm volatile(
        "mma.sync.aligned.m16n8k16.row.col.f32.bf16.bf16.f32 "
        "{%0,%1,%2,%3}, {%4,%5,%6,%7}, {%8,%9}, {%0,%1,%2,%3};"
        : "+f"(c[0]), "+f"(c[1]), "+f"(c[2]), "+f"(c[3])
        : "r"(a[0]), "r"(a[1]), "r"(a[2]), "r"(a[3]), "r"(b0), "r"(b1));
}
DEVFN void ldsm4(uint32_t r[4], uint32_t addr) {
    asm volatile("ldmatrix.sync.aligned.m8n8.x4.shared.b16 {%0,%1,%2,%3}, [%4];"
        : "=r"(r[0]), "=r"(r[1]), "=r"(r[2]), "=r"(r[3]) : "r"(addr));
}
DEVFN uint32_t f2u(float x) { return __float_as_uint(x); }

// ---------------- all-weights f32 -> bf16 (RNE), single launch ---------------
__global__ void __launch_bounds__(256) wcvt_all(
    const float4* __restrict__ w0, const float4* __restrict__ w1,
    const float4* __restrict__ w2, const float4* __restrict__ w3,
    uint2* __restrict__ d0, uint2* __restrict__ d1,
    uint2* __restrict__ d2, uint2* __restrict__ d3)
{
    int i = blockIdx.x * 256 + threadIdx.x;
    const float4* s; uint2* d; int j;
    if      (i <  49152) { s = w0; d = d0; j = i; }
    else if (i <  65536) { s = w1; d = d1; j = i - 49152; }
    else if (i < 131072) { s = w2; d = d2; j = i - 65536; }
    else                 { s = w3; d = d3; j = i - 131072; }
    float4 v = s[j];
    uint2 o; o.x = bfp(v.x, v.y); o.y = bfp(v.z, v.w);
    d[j] = o;
}

// ---------------- fused attention bias tiles ---------------------------------
__global__ void __launch_bounds__(256) bias_prep(
    const float* __restrict__ rel_bias, const float* __restrict__ mask,
    float* __restrict__ btile)
{
    int h = blockIdx.x >> 6;
    int widx = blockIdx.x & 63;
    float* dst = btile + (size_t)blockIdx.x * (49 * 56);
    const float* mrow = mask + (size_t)widx * 2401;
    for (int e = threadIdx.x; e < 49 * 56; e += 256) {
        int row = e / 56, col = e - row * 56;
        float v = -1e30f;
        if (col < 49) {
            int qi = row / 7, qj = row - qi * 7;
            int ki = col / 7, kj = col - ki * 7;
            int ridx = (qi - ki + 6) * 13 + (qj - kj + 6);
            v = rel_bias[ridx * 8 + h] + mrow[row * 49 + col];
        }
        dst[e] = v;
    }
}

// ---------------- LayerNorm (warp/row; bf16 output) --------------------------
__global__ void __launch_bounds__(256) ln_kernel(
    const float* __restrict__ in, __nv_bfloat16* __restrict__ out,
    const float* __restrict__ gamma, const float* __restrict__ beta,
    int shifted)
{
    int warp = threadIdx.x >> 5, lane = threadIdx.x & 31;
    int t = blockIdx.x * 8 + warp;
    int in_row, out_row;
    if (shifted) {
        int b = t / 3136; int rem = t - b * 3136;
        int i = rem / 56; int j = rem - i * 56;
        int si = i + 3; if (si >= 56) si -= 56;
        int sj = j + 3; if (sj >= 56) sj -= 56;
        in_row = b * 3136 + si * 56 + sj;
        int wb = b * 64 + (i / 7) * 8 + (j / 7);
        int n  = (i % 7) * 7 + (j % 7);
        out_row = wb * 49 + n;
    } else {
        in_row = out_row = t;
    }
    const float4* ip = (const float4*)(in + (size_t)in_row * 256);
    float4 a = ip[lane], b4 = ip[lane + 32];
    float s  = a.x + a.y + a.z + a.w + b4.x + b4.y + b4.z + b4.w;
    float sq = a.x*a.x + a.y*a.y + a.z*a.z + a.w*a.w
             + b4.x*b4.x + b4.y*b4.y + b4.z*b4.z + b4.w*b4.w;
    #pragma unroll
    for (int o = 16; o; o >>= 1) {
        s  += __shfl_xor_sync(0xffffffffu, s,  o);
        sq += __shfl_xor_sync(0xffffffffu, sq, o);
    }
    float mu   = s * (1.0f / 256.0f);
    float var  = sq * (1.0f / 256.0f) - mu * mu;
    float rstd = rsqrtf(var + 1e-5f);
    float4 g0 = ((const float4*)gamma)[lane], g1 = ((const float4*)gamma)[lane + 32];
    float4 e0 = ((const float4*)beta)[lane],  e1 = ((const float4*)beta)[lane + 32];
    uint2* op = (uint2*)(out + (size_t)out_row * 256);
    uint2 w0, w1;
    w0.x = bfp((a.x - mu) * rstd * g0.x + e0.x, (a.y - mu) * rstd * g0.y + e0.y);
    w0.y = bfp((a.z - mu) * rstd * g0.z + e0.z, (a.w - mu) * rstd * g0.w + e0.w);
    w1.x = bfp((b4.x - mu) * rstd * g1.x + e1.x, (b4.y - mu) * rstd * g1.y + e1.y);
    w1.y = bfp((b4.z - mu) * rstd * g1.z + e1.z, (b4.w - mu) * rstd * g1.w + e1.w);
    op[lane] = w0; op[lane + 32] = w1;
}

// ---------------- Tensor-core windowed attention (tf32; bf16 output) ---------
__global__ void __launch_bounds__(128, 6) attn_mma(const float* __restrict__ btile)
{
    int wb = blockIdx.x >> 3;
    int h  = blockIdx.x & 7;
    __shared__ float smem[6144];    // 24KB
    float* qs = smem;               // [64*32]
    float* ks = smem + 2048;        // [56*32]
    float* vt = smem + 4096;        // [32*64]
    float* sc = smem;               // [64*64] overlays qs+ks

    const int t = threadIdx.x;
    const int l = t & 31, w = t >> 5;
    const int ra = l >> 2, ca = l & 3;
    const int mbase = w * 16;
    size_t base = (size_t)blockIdx.x * (49 * 32);
    const float* bt = btile + (size_t)(h * 64 + (wb & 63)) * (49 * 56);

    for (int idx = t; idx < 392; idx += 128) {
        int n = idx >> 3, d4 = (idx & 7) << 2;
        uint32_t wi = (uint32_t)(n << 5) + (d4 ^ ((n & 7) << 2));
        *(float4*)(qs + wi) = *(const float4*)(g_q + base + (n << 5) + d4);
        *(float4*)(ks + wi) = *(const float4*)(g_k + base + (n << 5) + d4);
        float4 vv = *(const float4*)(g_v + base + (n << 5) + d4);
        vt[((d4 + 0) << 6) + (n ^ (((d4 + 0) & 7) << 2))] = vv.x;
        vt[((d4 + 1) << 6) + (n ^ (((d4 + 1) & 7) << 2))] = vv.y;
        vt[((d4 + 2) << 6) + (n ^ (((d4 + 2) & 7) << 2))] = vv.z;
        vt[((d4 + 3) << 6) + (n ^ (((d4 + 3) & 7) << 2))] = vv.w;
    }
    for (int idx = t; idx < 56; idx += 128) {
        int row = 49 + (idx >> 3), d4 = (idx & 7) << 2;
        *(float4*)(ks + (row << 5) + (d4 ^ ((row & 7) << 2))) =
            make_float4(0.f, 0.f, 0.f, 0.f);
    }
    for (int idx = t; idx < 224; idx += 128) {
        int d = idx / 7, m2 = 49 + idx - d * 7;
        vt[(d << 6) + (m2 ^ ((d & 7) << 2))] = 0.f;
    }
    __syncthreads();

    const int r0 = mbase + ra, r1 = r0 + 8;
    const int x0 = (r0 & 7) << 2, x1 = (r1 & 7) << 2;

    float acc[7][4];
    #pragma unroll
    for (int nt = 0; nt < 7; nt++)
        #pragma unroll
        for (int j = 0; j < 4; j++) acc[nt][j] = 0.f;

    #pragma unroll
    for (int k0 = 0; k0 < 32; k0 += 8) {
        uint32_t af[4];
        af[0] = f2u(qs[(r0 << 5) + ((k0 + ca)     ^ x0)]);
        af[1] = f2u(qs[(r1 << 5) + ((k0 + ca)     ^ x1)]);
        af[2] = f2u(qs[(r0 << 5) + ((k0 + ca + 4) ^ x0)]);
        af[3] = f2u(qs[(r1 << 5) + ((k0 + ca + 4) ^ x1)]);
        #pragma unroll
        for (int nt = 0; nt < 7; nt++) {
            int n = nt * 8 + ra;
            int xn = (n & 7) << 2;
            uint32_t bf[2];
            bf[0] = f2u(ks[(n << 5) + ((k0 + ca)     ^ xn)]);
            bf[1] = f2u(ks[(n << 5) + ((k0 + ca + 4) ^ xn)]);
            mma8(acc[nt], af, bf);
        }
    }

    #pragma unroll
    for (int nt = 0; nt < 7; nt++) {
        int cb = nt * 8 + 2 * ca;
        if (r0 < 49) {
            float2 b0 = *(const float2*)(bt + r0 * 56 + cb);
            acc[nt][0] += b0.x; acc[nt][1] += b0.y;
        } else { acc[nt][0] = -1e30f; acc[nt][1] = -1e30f; }
        if (r1 < 49) {
            float2 b1 = *(const float2*)(bt + r1 * 56 + cb);
            acc[nt][2] += b1.x; acc[nt][3] += b1.y;
        } else { acc[nt][2] = -1e30f; acc[nt][3] = -1e30f; }
    }

    float m0 = -1e30f, m1 = -1e30f;
    #pragma unroll
    for (int nt = 0; nt < 7; nt++) {
        m0 = fmaxf(m0, fmaxf(acc[nt][0], acc[nt][1]));
        m1 = fmaxf(m1, fmaxf(acc[nt][2], acc[nt][3]));
    }
    m0 = fmaxf(m0, __shfl_xor_sync(0xffffffffu, m0, 1));
    m0 = fmaxf(m0, __shfl_xor_sync(0xffffffffu, m0, 2));
    m1 = fmaxf(m1, __shfl_xor_sync(0xffffffffu, m1, 1));
    m1 = fmaxf(m1, __shfl_xor_sync(0xffffffffu, m1, 2));
    float s0 = 0.f, s1 = 0.f;
    #pragma unroll
    for (int nt = 0; nt < 7; nt++) {
        acc[nt][0] = __expf(acc[nt][0] - m0); s0 += acc[nt][0];
        acc[nt][1] = __expf(acc[nt][1] - m0); s0 += acc[nt][1];
        acc[nt][2] = __expf(acc[nt][2] - m1); s1 += acc[nt][2];
        acc[nt][3] = __expf(acc[nt][3] - m1); s1 += acc[nt][3];
    }
    s0 += __shfl_xor_sync(0xffffffffu, s0, 1);
    s0 += __shfl_xor_sync(0xffffffffu, s0, 2);
    s1 += __shfl_xor_sync(0xffffffffu, s1, 1);
    s1 += __shfl_xor_sync(0xffffffffu, s1, 2);
    float i0 = 1.0f / s0, i1 = 1.0f / s1;

    __syncthreads();

    #pragma unroll
    for (int nt = 0; nt < 7; nt++) {
        int cb = nt * 8 + 2 * ca;
        *(float2*)(sc + (r0 << 6) + (cb ^ x0)) =
            make_float2(acc[nt][0] * i0, acc[nt][1] * i0);
        *(float2*)(sc + (r1 << 6) + (cb ^ x1)) =
            make_float2(acc[nt][2] * i1, acc[nt][3] * i1);
    }
    __syncthreads();

    float o[4][4];
    #pragma unroll
    for (int nt = 0; nt < 4; nt++)
        #pragma unroll
        for (int j = 0; j < 4; j++) o[nt][j] = 0.f;

    #pragma unroll
    for (int k0 = 0; k0 < 56; k0 += 8) {
        uint32_t af[4];
        af[0] = f2u(sc[(r0 << 6) + ((k0 + ca)     ^ x0)]);
        af[1] = f2u(sc[(r1 << 6) + ((k0 + ca)     ^ x1)]);
        af[2] = f2u(sc[(r0 << 6) + ((k0 + ca + 4) ^ x0)]);
        af[3] = f2u(sc[(r1 << 6) + ((k0 + ca + 4) ^ x1)]);
        #pragma unroll
        for (int nt = 0; nt < 4; nt++) {
            int n = nt * 8 + ra;
            int xn = (n & 7) << 2;
            uint32_t bf[2];
            bf[0] = f2u(vt[(n << 6) + ((k0 + ca)     ^ xn)]);
            bf[1] = f2u(vt[(n << 6) + ((k0 + ca + 4) ^ xn)]);
            mma8(o[nt], af, bf);
        }
    }

    // store O as bf16 (feeds proj GEMM)
    #pragma unroll
    for (int half = 0; half < 2; half++) {
        int row = mbase + ra + half * 8;
        if (row < 49) {
            __nv_bfloat16* dst = g_o_bf + ((size_t)(wb * 49 + row)) * 256 + h * 32;
            #pragma unroll
            for (int nt = 0; nt < 4; nt++) {
                int col = nt * 8 + 2 * ca;
                *(uint32_t*)(dst + col) =
                    bfp(o[nt][half * 2 + 0], o[nt][half * 2 + 1]);
            }
        }
    }
}

// ---------------- bf16 mma.sync GEMM NT, 128x128 tile, warp tile 64x64 -------
// 128 threads / 4 warps (2x2). K-chunk 64, 3-stage cp.async pipeline.
// Per kk-step per warp: 4 ldsm.x4 (A) + 4 ldsm.x4 (B, 2 n-tiles each) + 32 mma.
// MODE 0: QKV  (bias; scatter q*SCALE / k / v f32 (tf32-rounded) for attention)
// MODE 1: proj (bias; window-reverse + un-roll; + residual) -> f32
// MODE 2: fc1  (bias; exact GELU) -> bf16
// MODE 3: fc2  (bias; + residual) -> f32
constexpr int GEMM_SMEM = 98304;   // 3 stages x (16K A + 16K B)

template <int MODE>
__global__ void __launch_bounds__(128, 2) mma_gemm(
    const __nv_bfloat16* __restrict__ A, const __nv_bfloat16* __restrict__ B,
    const float* __restrict__ bias, const float* __restrict__ res,
    float* __restrict__ O0, float* __restrict__ O1, float* __restrict__ O2,
    __nv_bfloat16* __restrict__ Ob, int K, int ldo)
{
    extern __shared__ float dsm[];
    const int t = threadIdx.x;
    const int rowBase = blockIdx.y * 128;
    const int colBase = blockIdx.x * 128;
    const uint32_t sbase = smem_u32(dsm);

    // producer: thread t loads A row t and B row t (8 x 16B each per stage)
    const __nv_bfloat16* Ap = A + (size_t)(rowBase + t) * K;
    const __nv_bfloat16* Bp = B + (size_t)(colBase + t) * K;
    uint32_t poff[8];
    #pragma unroll
    for (int s = 0; s < 8; s++)
        poff[s] = swz((uint32_t)t * 128u + (uint32_t)s * 16u);

    const int T = K >> 6;   // K-chunks of 64
    #pragma unroll
    for (int p = 0; p < 2; p++) {
        uint32_t sA = sbase + (uint32_t)p * 32768u, sB = sA + 16384u;
        #pragma unroll
        for (int s = 0; s < 8; s++) {
            cp16(sA + poff[s], Ap + p * 64 + s * 8);
            cp16(sB + poff[s], Bp + p * 64 + s * 8);
        }
        cp_commit();
    }

    const int l = t & 31, w = t >> 5;
    const int wr = w >> 1, wc = w & 1;      // 2x2 warps, 64x64 warp tile
    const int ra = l >> 2, ca = l & 3;

    // ldmatrix addressing (g = lane>>3 selects the 8x8 matrix)
    // A .x4: m0: m+r @k0 | m1: m+8+r @k0 | m2: m+r @k0+8 | m3: m+8+r @k0+8
    // B .x4: m0: n+r @k0 | m1: n+r @k0+8 | m2: n+8+r @k0 | m3: n+8+r @k0+8
    const int r8 = l & 7, g8 = l >> 3;
    const uint32_t xw = (uint32_t)r8 << 2;
    const uint32_t aKC = (uint32_t)(g8 >> 1) * 4u;   // A: +8 k for matrices 2,3
    const uint32_t bKC = (uint32_t)(g8 & 1) * 4u;    // B: +8 k for matrices 1,3
    uint32_t aRow[4], bRow[4];
    #pragma unroll
    for (int mt = 0; mt < 4; mt++)
        aRow[mt] = (uint32_t)(wr * 64 + mt * 16 + (g8 & 1) * 8 + r8) * 128u;
    #pragma unroll
    for (int np = 0; np < 4; np++)
        bRow[np] = (uint32_t)(wc * 64 + np * 16 + (g8 >> 1) * 8 + r8) * 128u;

    float c[4][8][4];
    #pragma unroll
    for (int mt = 0; mt < 4; mt++)
        #pragma unroll
        for (int nt = 0; nt < 8; nt++)
            #pragma unroll
            for (int j = 0; j < 4; j++) c[mt][nt][j] = 0.f;

    int stage = 0;
    for (int i = 0; i < T; i++) {
        cp_wait<1>();
        __syncthreads();
        if (i + 2 < T) {
            int ws = stage + 2; if (ws >= 3) ws -= 3;
            uint32_t sA = sbase + (uint32_t)ws * 32768u, sB = sA + 16384u;
            #pragma unroll
            for (int s = 0; s < 8; s++) {
                cp16(sA + poff[s], Ap + (i + 2) * 64 + s * 8);
                cp16(sB + poff[s], Bp + (i + 2) * 64 + s * 8);
            }
        }
        cp_commit();

        const uint32_t AsB = sbase + (uint32_t)stage * 32768u;
        const uint32_t BsB = AsB + 16384u;
        #pragma unroll
        for (int kk = 0; kk < 4; kk++) {
            const uint32_t aOff = (((uint32_t)kk * 8u + aKC) ^ xw) * 4u;
            const uint32_t bOff = (((uint32_t)kk * 8u + bKC) ^ xw) * 4u;
            uint32_t af[4][4], bq[4][4];
            #pragma unroll
            for (int mt = 0; mt < 4; mt++)
                ldsm4(af[mt], AsB + aRow[mt] + aOff);
            #pragma unroll
            for (int np = 0; np < 4; np++)
                ldsm4(bq[np], BsB + bRow[np] + bOff);
            #pragma unroll
            for (int mt = 0; mt < 4; mt++)
                #pragma unroll
                for (int np = 0; np < 4; np++) {
                    mma16(c[mt][2 * np],     af[mt], bq[np][0], bq[np][1]);
                    mma16(c[mt][2 * np + 1], af[mt], bq[np][2], bq[np][3]);
                }
        }
        stage = (stage == 2) ? 0 : stage + 1;
    }

    // ---------------- epilogue ----------------
    #pragma unroll
    for (int mt = 0; mt < 4; mt++) {
        #pragma unroll
        for (int rr = 0; rr < 2; rr++) {
            const int gm = rowBase + wr * 64 + mt * 16 + ra + rr * 8;
            int wb = 0, n = 0; size_t orow = 0;
            if (MODE == 0) { wb = gm / 49; n = gm - wb * 49; }
            if (MODE == 1) {
                wb = gm / 49; n = gm - wb * 49;
                int b = wb >> 6; int widx = wb & 63;
                int ii = (widx >> 3) * 7 + n / 7;
                int jj = (widx & 7) * 7 + n % 7;
                int oi = ii + 3; if (oi >= 56) oi -= 56;
                int oj = jj + 3; if (oj >= 56) oj -= 56;
                orow = ((size_t)b * 3136 + oi * 56 + oj) * 256;
            }
            if (MODE == 2 || MODE == 3) orow = (size_t)gm * ldo;

            #pragma unroll
            for (int nt = 0; nt < 8; nt++) {
                const int gc = colBase + wc * 64 + nt * 8 + 2 * ca;
                float2 bb = *(const float2*)(bias + gc);
                float v0 = c[mt][nt][rr * 2 + 0] + bb.x;
                float v1 = c[mt][nt][rr * 2 + 1] + bb.y;

                if (MODE == 0) {
                    int part = gc >> 8;
                    int hh = (gc >> 5) & 7;
                    int dd = gc & 31;
                    float* Op = (part == 0) ? O0 : ((part == 1) ? O1 : O2);
                    if (part == 0) { v0 *= SCALE; v1 *= SCALE; }
                    *(float2*)(Op + (((size_t)wb * 8 + hh) * 49 + n) * 32 + dd)
                        = make_float2(to_tf32(v0), to_tf32(v1));
                } else if (MODE == 1) {
                    float2 rr2 = *(const float2*)(res + orow + gc);
                    *(float2*)(O0 + orow + gc) = make_float2(rr2.x + v0, rr2.y + v1);
                } else if (MODE == 2) {
                    v0 = 0.5f * v0 * (1.0f + erff(v0 * 0.70710678118654752f));
                    v1 = 0.5f * v1 * (1.0f + erff(v1 * 0.70710678118654752f));
                    *(uint32_t*)(Ob + orow + gc) = bfp(v0, v1);
                } else {
                    float2 rr2 = *(const float2*)(res + orow + gc);
                    *(float2*)(O0 + orow + gc) = make_float2(rr2.x + v0, rr2.y + v1);
                }
            }
        }
    }
}

// ----------------------------------------------------------------------------
extern "C" void kernel_launch(void* const* d_in, const int* in_sizes, int n_in,
                              void* d_out, int out_size)
{
    const float* x      = (const float*)d_in[0];
    const float* mask   = (const float*)d_in[1];
    const float* n1g    = (const float*)d_in[2];
    const float* n1b    = (const float*)d_in[3];
    const float* qkv_w  = (const float*)d_in[4];
    const float* qkv_b  = (const float*)d_in[5];
    const float* relb   = (const float*)d_in[6];
    const float* proj_w = (const float*)d_in[7];
    const float* proj_b = (const float*)d_in[8];
    const float* n2g    = (const float*)d_in[9];
    const float* n2b    = (const float*)d_in[10];
    const float* fc1_w  = (const float*)d_in[11];
    const float* fc1_b  = (const float*)d_in[12];
    const float* fc2_w  = (const float*)d_in[13];
    const float* fc2_b  = (const float*)d_in[14];
    float* out = (float*)d_out;

    float *p_q, *p_k, *p_v, *p_x2, *p_btile;
    __nv_bfloat16 *p_hw, *p_o, *p_h2n, *p_mlp;
    __nv_bfloat16 *p_wqkv, *p_wprj, *p_wfc1, *p_wfc2;
    cudaGetSymbolAddress((void**)&p_q,     g_q);
    cudaGetSymbolAddress((void**)&p_k,     g_k);
    cudaGetSymbolAddress((void**)&p_v,     g_v);
    cudaGetSymbolAddress((void**)&p_x2,    g_x2);
    cudaGetSymbolAddress((void**)&p_btile, g_btile);
    cudaGetSymbolAddress((void**)&p_hw,    g_hw_bf);
    cudaGetSymbolAddress((void**)&p_o,     g_o_bf);
    cudaGetSymbolAddress((void**)&p_h2n,   g_h2n_bf);
    cudaGetSymbolAddress((void**)&p_mlp,   g_mlp_bf);
    cudaGetSymbolAddress((void**)&p_wqkv,  g_wqkv_bf);
    cudaGetSymbolAddress((void**)&p_wprj,  g_wprj_bf);
    cudaGetSymbolAddress((void**)&p_wfc1,  g_wfc1_bf);
    cudaGetSymbolAddress((void**)&p_wfc2,  g_wfc2_bf);

    cudaFuncSetAttribute(mma_gemm<0>, cudaFuncAttributeMaxDynamicSharedMemorySize, GEMM_SMEM);
    cudaFuncSetAttribute(mma_gemm<1>, cudaFuncAttributeMaxDynamicSharedMemorySize, GEMM_SMEM);
    cudaFuncSetAttribute(mma_gemm<2>, cudaFuncAttributeMaxDynamicSharedMemorySize, GEMM_SMEM);
    cudaFuncSetAttribute(mma_gemm<3>, cudaFuncAttributeMaxDynamicSharedMemorySize, GEMM_SMEM);

    wcvt_all<<<768, 256>>>((const float4*)qkv_w, (const float4*)proj_w,
                           (const float4*)fc1_w, (const float4*)fc2_w,
                           (uint2*)p_wqkv, (uint2*)p_wprj,
                           (uint2*)p_wfc1, (uint2*)p_wfc2);
    bias_prep<<<512, 256>>>(relb, mask, p_btile);
    // 1. LN1 + shift + window partition -> bf16
    ln_kernel<<<TOKENS / 8, 256>>>(x, p_hw, n1g, n1b, 1);
    // 2. QKV (bf16 mma) -> q(scaled)/k/v f32 in (wb,h,n,d)
    mma_gemm<0><<<dim3(6, 392), 128, GEMM_SMEM>>>(p_hw, p_wqkv, qkv_b, nullptr,
                                                  p_q, p_k, p_v, nullptr, 256, 0);
    // 3. Windowed MSA (tf32 tensor-core) -> bf16
    attn_mma<<<8192, 128>>>(p_btile);
    // 4. proj (bf16 mma) + window-reverse + un-roll + residual(x) -> f32
    mma_gemm<1><<<dim3(2, 392), 128, GEMM_SMEM>>>(p_o, p_wprj, proj_b, x,
                                                  p_x2, nullptr, nullptr, nullptr, 256, 256);
    // 5. LN2 -> bf16
    ln_kernel<<<TOKENS / 8, 256>>>(p_x2, p_h2n, n2g, n2b, 0);
    // 6. fc1 (bf16 mma) + GELU -> bf16
    mma_gemm<2><<<dim3(8, 392), 128, GEMM_SMEM>>>(p_h2n, p_wfc1, fc1_b, nullptr,
                                                  nullptr, nullptr, nullptr, p_mlp, 256, 1024);
    // 7. fc2 (bf16 mma) + residual(x2) -> out
    mma_gemm<3><<<dim3(2, 392), 128, GEMM_SMEM>>>(p_mlp, p_wfc2, fc2_b, p_x2,
                                                  out, nullptr, nullptr, nullptr, 1024, 256);
}

// round 14
// speedup vs baseline: 1.3545x; 1.3545x over previous
#include <cuda_runtime.h>
#include <cuda_bf16.h>
#include <cstdint>

#define DEVFN __device__ __forceinline__

constexpr int TOKENS = 16 * 56 * 56;   // 50176
constexpr float SCALE = 0.17677669529663687f;   // 32^-0.5

// Scratch (static device arrays: allocation-free per harness rules)
__device__ float g_q   [TOKENS * 256];
__device__ float g_k   [TOKENS * 256];
__device__ float g_v   [TOKENS * 256];
__device__ float g_x2  [TOKENS * 256];
__device__ float g_btile[512 * 49 * 56];            // fused rel_bias+mask
__device__ __nv_bfloat16 g_hw_bf [TOKENS * 256];    // LN1 out (windowed)
__device__ __nv_bfloat16 g_o_bf  [TOKENS * 256];    // attention out
__device__ __nv_bfloat16 g_h2n_bf[TOKENS * 256];    // LN2 out
__device__ __nv_bfloat16 g_mlp_bf[TOKENS * 1024];   // fc1+gelu out
__device__ __nv_bfloat16 g_wqkv_bf[768 * 256];
__device__ __nv_bfloat16 g_wprj_bf[256 * 256];
__device__ __nv_bfloat16 g_wfc1_bf[1024 * 256];
__device__ __nv_bfloat16 g_wfc2_bf[256 * 1024];

// ------------------------------ PTX helpers ---------------------------------
DEVFN uint32_t smem_u32(const void* p) {
    uint32_t a;
    asm("{ .reg .u64 t; cvta.to.shared.u64 t, %1; cvt.u32.u64 %0, t; }"
        : "=r"(a) : "l"(p));
    return a;
}
DEVFN uint32_t swz(uint32_t o) { return o ^ ((o >> 3) & 0x70u); }
DEVFN void cp16(uint32_t dst, const void* src) {
    asm volatile("cp.async.cg.shared.global [%0], [%1], 16;" :: "r"(dst), "l"(src));
}
DEVFN void mbar_init(uint32_t a, uint32_t c) {
    asm volatile("mbarrier.init.shared.b64 [%0], %1;" :: "r"(a), "r"(c) : "memory");
}
DEVFN void mbar_arrive(uint32_t a) {
    asm volatile("mbarrier.arrive.shared.b64 _, [%0];" :: "r"(a) : "memory");
}
DEVFN void cp_arrive(uint32_t a) {
    // .noinc: arrival counts against the init count (plain form is inc+arrive = net 0)
    asm volatile("cp.async.mbarrier.arrive.noinc.shared.b64 [%0];" :: "r"(a) : "memory");
}
DEVFN void mbar_wait(uint32_t a, uint32_t par) {
    asm volatile(
        "{\n\t.reg .pred P;\n"
        "LAB_%=:\n\t"
        "mbarrier.try_wait.parity.acquire.cta.shared::cta.b64 P, [%0], %1, 0x989680;\n\t"
        "@!P bra LAB_%=;\n\t}"
        :: "r"(a), "r"(par) : "memory");
}
DEVFN float to_tf32(float x) {
    float r;
    asm("cvt.rna.tf32.f32 %0, %1;" : "=f"(r) : "f"(x));
    return r;
}
DEVFN uint32_t bfp(float a, float b) {   // pack 2 floats -> bf16x2 (RNE)
    __nv_bfloat162 t = __floats2bfloat162_rn(a, b);
    return *(uint32_t*)&t;
}
// tf32 mma (attention)
DEVFN void mma8(float c[4], const uint32_t a[4], const uint32_t b[2]) {
    asm volatile(
        "mma.sync.aligned.m16n8k8.row.col.f32.tf32.tf32.f32 "
        "{%0,%1,%2,%3}, {%4,%5,%6,%7}, {%8,%9}, {%0,%1,%2,%3};"
        : "+f"(c[0]), "+f"(c[1]), "+f"(c[2]), "+f"(c[3])
        : "r"(a[0]), "r"(a[1]), "r"(a[2]), "r"(a[3]), "r"(b[0]), "r"(b[1]));
}
// bf16 mma (GEMMs): K=16 per instruction
DEVFN void mma16(float c[4], const uint32_t a[4], const uint32_t b0, const uint32_t b1) {
    asm volatile(
        "mma.sync.aligned.m16n8k16.row.col.f32.bf16.bf16.f32 "
        "{%0,%1,%2,%3}, {%4,%5,%6,%7}, {%8,%9}, {%0,%1,%2,%3};"
        : "+f"(c[0]), "+f"(c[1]), "+f"(c[2]), "+f"(c[3])
        : "r"(a[0]), "r"(a[1]), "r"(a[2]), "r"(a[3]), "r"(b0), "r"(b1));
}
DEVFN void ldsm4(uint32_t r[4], uint32_t addr) {
    asm volatile("ldmatrix.sync.aligned.m8n8.x4.shared.b16 {%0,%1,%2,%3}, [%4];"
        : "=r"(r[0]), "=r"(r[1]), "=r"(r[2]), "=r"(r[3]) : "r"(addr));
}
DEVFN void ldsm2(uint32_t r[2], uint32_t addr) {
    asm volatile("ldmatrix.sync.aligned.m8n8.x2.shared.b16 {%0,%1}, [%2];"
        : "=r"(r[0]), "=r"(r[1]) : "r"(addr));
}
DEVFN uint32_t f2u(float x) { return __float_as_uint(x); }

// ---------------- fused prep: bias tiles (blocks 0-511) + weight cvt (512+) --
__global__ void __launch_bounds__(256) prep_all(
    const float* __restrict__ rel_bias, const float* __restrict__ mask,
    float* __restrict__ btile,
    const float4* __restrict__ w0, const float4* __restrict__ w1,
    const float4* __restrict__ w2, const float4* __restrict__ w3,
    uint2* __restrict__ d0, uint2* __restrict__ d1,
    uint2* __restrict__ d2, uint2* __restrict__ d3)
{
    int bid = blockIdx.x;
    if (bid < 512) {
        int h = bid >> 6;
        int widx = bid & 63;
        float* dst = btile + (size_t)bid * (49 * 56);
        const float* mrow = mask + (size_t)widx * 2401;
        for (int e = threadIdx.x; e < 49 * 56; e += 256) {
            int row = e / 56, col = e - row * 56;
            float v = -1e30f;
            if (col < 49) {
                int qi = row / 7, qj = row - qi * 7;
                int ki = col / 7, kj = col - ki * 7;
                int ridx = (qi - ki + 6) * 13 + (qj - kj + 6);
                v = rel_bias[ridx * 8 + h] + mrow[row * 49 + col];
            }
            dst[e] = v;
        }
    } else {
        int i = (bid - 512) * 256 + threadIdx.x;
        const float4* s; uint2* d; int j;
        if      (i <  49152) { s = w0; d = d0; j = i; }
        else if (i <  65536) { s = w1; d = d1; j = i - 49152; }
        else if (i < 131072) { s = w2; d = d2; j = i - 65536; }
        else                 { s = w3; d = d3; j = i - 131072; }
        float4 v = s[j];
        uint2 o; o.x = bfp(v.x, v.y); o.y = bfp(v.z, v.w);
        d[j] = o;
    }
}

// ---------------- LayerNorm (warp/row; bf16 output) --------------------------
__global__ void __launch_bounds__(256) ln_kernel(
    const float* __restrict__ in, __nv_bfloat16* __restrict__ out,
    const float* __restrict__ gamma, const float* __restrict__ beta,
    int shifted)
{
    int warp = threadIdx.x >> 5, lane = threadIdx.x & 31;
    int t = blockIdx.x * 8 + warp;
    int in_row, out_row;
    if (shifted) {
        int b = t / 3136; int rem = t - b * 3136;
        int i = rem / 56; int j = rem - i * 56;
        int si = i + 3; if (si >= 56) si -= 56;
        int sj = j + 3; if (sj >= 56) sj -= 56;
        in_row = b * 3136 + si * 56 + sj;
        int wb = b * 64 + (i / 7) * 8 + (j / 7);
        int n  = (i % 7) * 7 + (j % 7);
        out_row = wb * 49 + n;
    } else {
        in_row = out_row = t;
    }
    const float4* ip = (const float4*)(in + (size_t)in_row * 256);
    float4 a = ip[lane], b4 = ip[lane + 32];
    float s  = a.x + a.y + a.z + a.w + b4.x + b4.y + b4.z + b4.w;
    float sq = a.x*a.x + a.y*a.y + a.z*a.z + a.w*a.w
             + b4.x*b4.x + b4.y*b4.y + b4.z*b4.z + b4.w*b4.w;
    #pragma unroll
    for (int o = 16; o; o >>= 1) {
        s  += __shfl_xor_sync(0xffffffffu, s,  o);
        sq += __shfl_xor_sync(0xffffffffu, sq, o);
    }
    float mu   = s * (1.0f / 256.0f);
    float var  = sq * (1.0f / 256.0f) - mu * mu;
    float rstd = rsqrtf(var + 1e-5f);
    float4 g0 = ((const float4*)gamma)[lane], g1 = ((const float4*)gamma)[lane + 32];
    float4 e0 = ((const float4*)beta)[lane],  e1 = ((const float4*)beta)[lane + 32];
    uint2* op = (uint2*)(out + (size_t)out_row * 256);
    uint2 w0, w1;
    w0.x = bfp((a.x - mu) * rstd * g0.x + e0.x, (a.y - mu) * rstd * g0.y + e0.y);
    w0.y = bfp((a.z - mu) * rstd * g0.z + e0.z, (a.w - mu) * rstd * g0.w + e0.w);
    w1.x = bfp((b4.x - mu) * rstd * g1.x + e1.x, (b4.y - mu) * rstd * g1.y + e1.y);
    w1.y = bfp((b4.z - mu) * rstd * g1.z + e1.z, (b4.w - mu) * rstd * g1.w + e1.w);
    op[lane] = w0; op[lane + 32] = w1;
}

// ---------------- Tensor-core windowed attention (tf32; bf16 output) ---------
__global__ void __launch_bounds__(128, 6) attn_mma(const float* __restrict__ btile)
{
    int wb = blockIdx.x >> 3;
    int h  = blockIdx.x & 7;
    __shared__ float smem[6144];    // 24KB
    float* qs = smem;               // [64*32]
    float* ks = smem + 2048;        // [56*32]
    float* vt = smem + 4096;        // [32*64]
    float* sc = smem;               // [64*64] overlays qs+ks

    const int t = threadIdx.x;
    const int l = t & 31, w = t >> 5;
    const int ra = l >> 2, ca = l & 3;
    const int mbase = w * 16;
    size_t base = (size_t)blockIdx.x * (49 * 32);
    const float* bt = btile + (size_t)(h * 64 + (wb & 63)) * (49 * 56);

    for (int idx = t; idx < 392; idx += 128) {
        int n = idx >> 3, d4 = (idx & 7) << 2;
        uint32_t wi = (uint32_t)(n << 5) + (d4 ^ ((n & 7) << 2));
        *(float4*)(qs + wi) = *(const float4*)(g_q + base + (n << 5) + d4);
        *(float4*)(ks + wi) = *(const float4*)(g_k + base + (n << 5) + d4);
        float4 vv = *(const float4*)(g_v + base + (n << 5) + d4);
        vt[((d4 + 0) << 6) + (n ^ (((d4 + 0) & 7) << 2))] = vv.x;
        vt[((d4 + 1) << 6) + (n ^ (((d4 + 1) & 7) << 2))] = vv.y;
        vt[((d4 + 2) << 6) + (n ^ (((d4 + 2) & 7) << 2))] = vv.z;
        vt[((d4 + 3) << 6) + (n ^ (((d4 + 3) & 7) << 2))] = vv.w;
    }
    for (int idx = t; idx < 56; idx += 128) {
        int row = 49 + (idx >> 3), d4 = (idx & 7) << 2;
        *(float4*)(ks + (row << 5) + (d4 ^ ((row & 7) << 2))) =
            make_float4(0.f, 0.f, 0.f, 0.f);
    }
    for (int idx = t; idx < 224; idx += 128) {
        int d = idx / 7, m2 = 49 + idx - d * 7;
        vt[(d << 6) + (m2 ^ ((d & 7) << 2))] = 0.f;
    }
    __syncthreads();

    const int r0 = mbase + ra, r1 = r0 + 8;
    const int x0 = (r0 & 7) << 2, x1 = (r1 & 7) << 2;

    float acc[7][4];
    #pragma unroll
    for (int nt = 0; nt < 7; nt++)
        #pragma unroll
        for (int j = 0; j < 4; j++) acc[nt][j] = 0.f;

    #pragma unroll
    for (int k0 = 0; k0 < 32; k0 += 8) {
        uint32_t af[4];
        af[0] = f2u(qs[(r0 << 5) + ((k0 + ca)     ^ x0)]);
        af[1] = f2u(qs[(r1 << 5) + ((k0 + ca)     ^ x1)]);
        af[2] = f2u(qs[(r0 << 5) + ((k0 + ca + 4) ^ x0)]);
        af[3] = f2u(qs[(r1 << 5) + ((k0 + ca + 4) ^ x1)]);
        #pragma unroll
        for (int nt = 0; nt < 7; nt++) {
            int n = nt * 8 + ra;
            int xn = (n & 7) << 2;
            uint32_t bf[2];
            bf[0] = f2u(ks[(n << 5) + ((k0 + ca)     ^ xn)]);
            bf[1] = f2u(ks[(n << 5) + ((k0 + ca + 4) ^ xn)]);
            mma8(acc[nt], af, bf);
        }
    }

    #pragma unroll
    for (int nt = 0; nt < 7; nt++) {
        int cb = nt * 8 + 2 * ca;
        if (r0 < 49) {
            float2 b0 = *(const float2*)(bt + r0 * 56 + cb);
            acc[nt][0] += b0.x; acc[nt][1] += b0.y;
        } else { acc[nt][0] = -1e30f; acc[nt][1] = -1e30f; }
        if (r1 < 49) {
            float2 b1 = *(const float2*)(bt + r1 * 56 + cb);
            acc[nt][2] += b1.x; acc[nt][3] += b1.y;
        } else { acc[nt][2] = -1e30f; acc[nt][3] = -1e30f; }
    }

    float m0 = -1e30f, m1 = -1e30f;
    #pragma unroll
    for (int nt = 0; nt < 7; nt++) {
        m0 = fmaxf(m0, fmaxf(acc[nt][0], acc[nt][1]));
        m1 = fmaxf(m1, fmaxf(acc[nt][2], acc[nt][3]));
    }
    m0 = fmaxf(m0, __shfl_xor_sync(0xffffffffu, m0, 1));
    m0 = fmaxf(m0, __shfl_xor_sync(0xffffffffu, m0, 2));
    m1 = fmaxf(m1, __shfl_xor_sync(0xffffffffu, m1, 1));
    m1 = fmaxf(m1, __shfl_xor_sync(0xffffffffu, m1, 2));
    float s0 = 0.f, s1 = 0.f;
    #pragma unroll
    for (int nt = 0; nt < 7; nt++) {
        acc[nt][0] = __expf(acc[nt][0] - m0); s0 += acc[nt][0];
        acc[nt][1] = __expf(acc[nt][1] - m0); s0 += acc[nt][1];
        acc[nt][2] = __expf(acc[nt][2] - m1); s1 += acc[nt][2];
        acc[nt][3] = __expf(acc[nt][3] - m1); s1 += acc[nt][3];
    }
    s0 += __shfl_xor_sync(0xffffffffu, s0, 1);
    s0 += __shfl_xor_sync(0xffffffffu, s0, 2);
    s1 += __shfl_xor_sync(0xffffffffu, s1, 1);
    s1 += __shfl_xor_sync(0xffffffffu, s1, 2);
    float i0 = 1.0f / s0, i1 = 1.0f / s1;

    __syncthreads();

    #pragma unroll
    for (int nt = 0; nt < 7; nt++) {
        int cb = nt * 8 + 2 * ca;
        *(float2*)(sc + (r0 << 6) + (cb ^ x0)) =
            make_float2(acc[nt][0] * i0, acc[nt][1] * i0);
        *(float2*)(sc + (r1 << 6) + (cb ^ x1)) =
            make_float2(acc[nt][2] * i1, acc[nt][3] * i1);
    }
    __syncthreads();

    float o[4][4];
    #pragma unroll
    for (int nt = 0; nt < 4; nt++)
        #pragma unroll
        for (int j = 0; j < 4; j++) o[nt][j] = 0.f;

    #pragma unroll
    for (int k0 = 0; k0 < 56; k0 += 8) {
        uint32_t af[4];
        af[0] = f2u(sc[(r0 << 6) + ((k0 + ca)     ^ x0)]);
        af[1] = f2u(sc[(r1 << 6) + ((k0 + ca)     ^ x1)]);
        af[2] = f2u(sc[(r0 << 6) + ((k0 + ca + 4) ^ x0)]);
        af[3] = f2u(sc[(r1 << 6) + ((k0 + ca + 4) ^ x1)]);
        #pragma unroll
        for (int nt = 0; nt < 4; nt++) {
            int n = nt * 8 + ra;
            int xn = (n & 7) << 2;
            uint32_t bf[2];
            bf[0] = f2u(vt[(n << 6) + ((k0 + ca)     ^ xn)]);
            bf[1] = f2u(vt[(n << 6) + ((k0 + ca + 4) ^ xn)]);
            mma8(o[nt], af, bf);
        }
    }

    // store O as bf16 (feeds proj GEMM)
    #pragma unroll
    for (int half = 0; half < 2; half++) {
        int row = mbase + ra + half * 8;
        if (row < 49) {
            __nv_bfloat16* dst = g_o_bf + ((size_t)(wb * 49 + row)) * 256 + h * 32;
            #pragma unroll
            for (int nt = 0; nt < 4; nt++) {
                int col = nt * 8 + 2 * ca;
                *(uint32_t*)(dst + col) =
                    bfp(o[nt][half * 2 + 0], o[nt][half * 2 + 1]);
            }
        }
    }
}

// ---------------- bf16 mma.sync GEMM NT, 128x128 tile, K-chunk 64 ------------
// 3-stage pipeline with PER-STAGE MBARRIERS (no block-wide sync in mainloop):
// full[s] <- cp.async.mbarrier.arrive.NOINC (256 deferred thread-arrivals)
// free[s] <- mbarrier.arrive after the stage's last fragment read
// Warps skew up to a full stage -> LDSM and HMMA issue overlap across warps.
// MODE 0: QKV  MODE 1: proj  MODE 2: fc1+GELU  MODE 3: fc2+residual
constexpr int GEMM_SMEM = 98304 + 64;   // 3 x 32KB stages + 6 mbarriers

template <int MODE>
__global__ void __launch_bounds__(256, 2) mma_gemm(
    const __nv_bfloat16* __restrict__ A, const __nv_bfloat16* __restrict__ B,
    const float* __restrict__ bias, const float* __restrict__ res,
    float* __restrict__ O0, float* __restrict__ O1, float* __restrict__ O2,
    __nv_bfloat16* __restrict__ Ob, int K, int ldo)
{
    extern __shared__ float dsm[];
    const int t = threadIdx.x;
    const int rowBase = blockIdx.y * 128;
    const int colBase = blockIdx.x * 128;
    const uint32_t sbase = smem_u32(dsm);
    const uint32_t mb = sbase + 98304u;     // full[0..2] @ +0,8,16; free[0..2] @ +24,32,40

    if (t == 0) {
        #pragma unroll
        for (int s2 = 0; s2 < 3; s2++) {
            mbar_init(mb + 8u * s2, 256);
            mbar_init(mb + 24u + 8u * s2, 256);
        }
    }
    __syncthreads();

    // producer: thread t loads row (t>>1), 64B half (t&1) as 4x16B
    const int pr = t >> 1, ph = t & 1;
    const __nv_bfloat16* Ap = A + (size_t)(rowBase + pr) * K + ph * 32;
    const __nv_bfloat16* Bp = B + (size_t)(colBase + pr) * K + ph * 32;
    uint32_t poff[4];
    #pragma unroll
    for (int s = 0; s < 4; s++)
        poff[s] = swz((uint32_t)pr * 128u + (uint32_t)(ph * 4 + s) * 16u);

    const int T = K >> 6;   // K-chunks of 64
    #pragma unroll
    for (int p = 0; p < 2; p++) {
        uint32_t sA = sbase + (uint32_t)p * 32768u, sB = sA + 16384u;
        #pragma unroll
        for (int s = 0; s < 4; s++) {
            cp16(sA + poff[s], Ap + p * 64 + s * 8);
            cp16(sB + poff[s], Bp + p * 64 + s * 8);
        }
        cp_arrive(mb + 8u * (uint32_t)p);
    }

    const int l = t & 31, w = t >> 5;
    const int wr = w >> 2, wc = w & 3;
    const int ra = l >> 2, ca = l & 3;

    // ldmatrix addressing
    const int r8 = l & 7, g8 = l >> 3;
    const uint32_t xw = (uint32_t)r8 << 2;
    const uint32_t aKC = (uint32_t)(g8 >> 1) * 4u;
    const uint32_t bKC = (uint32_t)(g8 & 1) * 4u;
    uint32_t aRow[4], bRow[4];
    #pragma unroll
    for (int mt = 0; mt < 4; mt++)
        aRow[mt] = (uint32_t)(wr * 64 + mt * 16 + (g8 & 1) * 8 + r8) * 128u;
    #pragma unroll
    for (int nt = 0; nt < 4; nt++)
        bRow[nt] = (uint32_t)(wc * 32 + nt * 8 + r8) * 128u;

    float c[4][4][4];
    #pragma unroll
    for (int mt = 0; mt < 4; mt++)
        #pragma unroll
        for (int nt = 0; nt < 4; nt++)
            #pragma unroll
            for (int j = 0; j < 4; j++) c[mt][nt][j] = 0.f;

    int r = 0, qd = 0;          // i = 3*qd + r
    for (int i = 0; i < T; i++) {
        // wait stage-r data (fill n == use n == i/3; parity qd&1)
        mbar_wait(mb + 8u * (uint32_t)r, (uint32_t)(qd & 1));

        // prefetch chunk i+2 into stage ws=(i+2)%3 (consumed last at iter i-1)
        if (i + 2 < T) {
            int ws = (r == 0) ? 2 : r - 1;
            if (i >= 1) {
                int pfree = ((r >= 1) ? qd : qd - 1) & 1;   // ((i-1)/3)&1
                mbar_wait(mb + 24u + 8u * (uint32_t)ws, (uint32_t)pfree);
            }
            uint32_t sA = sbase + (uint32_t)ws * 32768u, sB = sA + 16384u;
            #pragma unroll
            for (int s = 0; s < 4; s++) {
                cp16(sA + poff[s], Ap + (i + 2) * 64 + s * 8);
                cp16(sB + poff[s], Bp + (i + 2) * 64 + s * 8);
            }
            cp_arrive(mb + 8u * (uint32_t)ws);
        }

        const uint32_t AsB = sbase + (uint32_t)r * 32768u;
        const uint32_t BsB = AsB + 16384u;
        #pragma unroll
        for (int kk = 0; kk < 4; kk++) {
            const uint32_t aOff = (((uint32_t)kk * 8u + aKC) ^ xw) * 4u;
            const uint32_t bOff = (((uint32_t)kk * 8u + bKC) ^ xw) * 4u;
            uint32_t af[4][4], bf[4][2];
            #pragma unroll
            for (int mt = 0; mt < 4; mt++)
                ldsm4(af[mt], AsB + aRow[mt] + aOff);
            #pragma unroll
            for (int nt = 0; nt < 4; nt++)
                ldsm2(bf[nt], BsB + bRow[nt] + bOff);
            #pragma unroll
            for (int mt = 0; mt < 4; mt++)
                #pragma unroll
                for (int nt = 0; nt < 4; nt++)
                    mma16(c[mt][nt], af[mt], bf[nt][0], bf[nt][1]);
        }
        // release stage r
        mbar_arrive(mb + 24u + 8u * (uint32_t)r);

        if (++r == 3) { r = 0; qd++; }
    }

    // ---------------- epilogue ----------------
    #pragma unroll
    for (int mt = 0; mt < 4; mt++) {
        #pragma unroll
        for (int rr = 0; rr < 2; rr++) {
            const int gm = rowBase + wr * 64 + mt * 16 + ra + rr * 8;
            int wb = 0, n = 0; size_t orow = 0;
            if (MODE == 0) { wb = gm / 49; n = gm - wb * 49; }
            if (MODE == 1) {
                wb = gm / 49; n = gm - wb * 49;
                int b = wb >> 6; int widx = wb & 63;
                int ii = (widx >> 3) * 7 + n / 7;
                int jj = (widx & 7) * 7 + n % 7;
                int oi = ii + 3; if (oi >= 56) oi -= 56;
                int oj = jj + 3; if (oj >= 56) oj -= 56;
                orow = ((size_t)b * 3136 + oi * 56 + oj) * 256;
            }
            if (MODE == 2 || MODE == 3) orow = (size_t)gm * ldo;

            #pragma unroll
            for (int nt = 0; nt < 4; nt++) {
                const int gc = colBase + wc * 32 + nt * 8 + 2 * ca;
                float2 bb = *(const float2*)(bias + gc);
                float v0 = c[mt][nt][rr * 2 + 0] + bb.x;
                float v1 = c[mt][nt][rr * 2 + 1] + bb.y;

                if (MODE == 0) {
                    int part = gc >> 8;
                    int hh = (gc >> 5) & 7;
                    int dd = gc & 31;
                    float* Op = (part == 0) ? O0 : ((part == 1) ? O1 : O2);
                    if (part == 0) { v0 *= SCALE; v1 *= SCALE; }
                    *(float2*)(Op + (((size_t)wb * 8 + hh) * 49 + n) * 32 + dd)
                        = make_float2(to_tf32(v0), to_tf32(v1));
                } else if (MODE == 1) {
                    float2 rr2 = *(const float2*)(res + orow + gc);
                    *(float2*)(O0 + orow + gc) = make_float2(rr2.x + v0, rr2.y + v1);
                } else if (MODE == 2) {
                    v0 = 0.5f * v0 * (1.0f + erff(v0 * 0.70710678118654752f));
                    v1 = 0.5f * v1 * (1.0f + erff(v1 * 0.70710678118654752f));
                    *(uint32_t*)(Ob + orow + gc) = bfp(v0, v1);
                } else {
                    float2 rr2 = *(const float2*)(res + orow + gc);
                    *(float2*)(O0 + orow + gc) = make_float2(rr2.x + v0, rr2.y + v1);
                }
            }
        }
    }
}

// ----------------------------------------------------------------------------
extern "C" void kernel_launch(void* const* d_in, const int* in_sizes, int n_in,
                              void* d_out, int out_size)
{
    const float* x      = (const float*)d_in[0];
    const float* mask   = (const float*)d_in[1];
    const float* n1g    = (const float*)d_in[2];
    const float* n1b    = (const float*)d_in[3];
    const float* qkv_w  = (const float*)d_in[4];
    const float* qkv_b  = (const float*)d_in[5];
    const float* relb   = (const float*)d_in[6];
    const float* proj_w = (const float*)d_in[7];
    const float* proj_b = (const float*)d_in[8];
    const float* n2g    = (const float*)d_in[9];
    const float* n2b    = (const float*)d_in[10];
    const float* fc1_w  = (const float*)d_in[11];
    const float* fc1_b  = (const float*)d_in[12];
    const float* fc2_w  = (const float*)d_in[13];
    const float* fc2_b  = (const float*)d_in[14];
    float* out = (float*)d_out;

    float *p_q, *p_k, *p_v, *p_x2, *p_btile;
    __nv_bfloat16 *p_hw, *p_o, *p_h2n, *p_mlp;
    __nv_bfloat16 *p_wqkv, *p_wprj, *p_wfc1, *p_wfc2;
    cudaGetSymbolAddress((void**)&p_q,     g_q);
    cudaGetSymbolAddress((void**)&p_k,     g_k);
    cudaGetSymbolAddress((void**)&p_v,     g_v);
    cudaGetSymbolAddress((void**)&p_x2,    g_x2);
    cudaGetSymbolAddress((void**)&p_btile, g_btile);
    cudaGetSymbolAddress((void**)&p_hw,    g_hw_bf);
    cudaGetSymbolAddress((void**)&p_o,     g_o_bf);
    cudaGetSymbolAddress((void**)&p_h2n,   g_h2n_bf);
    cudaGetSymbolAddress((void**)&p_mlp,   g_mlp_bf);
    cudaGetSymbolAddress((void**)&p_wqkv,  g_wqkv_bf);
    cudaGetSymbolAddress((void**)&p_wprj,  g_wprj_bf);
    cudaGetSymbolAddress((void**)&p_wfc1,  g_wfc1_bf);
    cudaGetSymbolAddress((void**)&p_wfc2,  g_wfc2_bf);

    cudaFuncSetAttribute(mma_gemm<0>, cudaFuncAttributeMaxDynamicSharedMemorySize, GEMM_SMEM);
    cudaFuncSetAttribute(mma_gemm<1>, cudaFuncAttributeMaxDynamicSharedMemorySize, GEMM_SMEM);
    cudaFuncSetAttribute(mma_gemm<2>, cudaFuncAttributeMaxDynamicSharedMemorySize, GEMM_SMEM);
    cudaFuncSetAttribute(mma_gemm<3>, cudaFuncAttributeMaxDynamicSharedMemorySize, GEMM_SMEM);

    // 0. fused prep: bias tiles + weight bf16 conversion
    prep_all<<<1280, 256>>>(relb, mask, p_btile,
                            (const float4*)qkv_w, (const float4*)proj_w,
                            (const float4*)fc1_w, (const float4*)fc2_w,
                            (uint2*)p_wqkv, (uint2*)p_wprj,
                            (uint2*)p_wfc1, (uint2*)p_wfc2);
    // 1. LN1 + shift + window partition -> bf16
    ln_kernel<<<TOKENS / 8, 256>>>(x, p_hw, n1g, n1b, 1);
    // 2. QKV (bf16 mma) -> q(scaled)/k/v f32 in (wb,h,n,d)
    mma_gemm<0><<<dim3(6, 392), 256, GEMM_SMEM>>>(p_hw, p_wqkv, qkv_b, nullptr,
                                                  p_q, p_k, p_v, nullptr, 256, 0);
    // 3. Windowed MSA (tf32 tensor-core) -> bf16
    attn_mma<<<8192, 128>>>(p_btile);
    // 4. proj (bf16 mma) + window-reverse + un-roll + residual(x) -> f32
    mma_gemm<1><<<dim3(2, 392), 256, GEMM_SMEM>>>(p_o, p_wprj, proj_b, x,
                                                  p_x2, nullptr, nullptr, nullptr, 256, 256);
    // 5. LN2 -> bf16
    ln_kernel<<<TOKENS / 8, 256>>>(p_x2, p_h2n, n2g, n2b, 0);
    // 6. fc1 (bf16 mma) + GELU -> bf16
    mma_gemm<2><<<dim3(8, 392), 256, GEMM_SMEM>>>(p_h2n, p_wfc1, fc1_b, nullptr,
                                                  nullptr, nullptr, nullptr, p_mlp, 256, 1024);
    // 7. fc2 (bf16 mma) + residual(x2) -> out
    mma_gemm<3><<<dim3(2, 392), 256, GEMM_SMEM>>>(p_mlp, p_wfc2, fc2_b, p_x2,
                                                  out, nullptr, nullptr, nullptr, 1024, 256);
}

// round 16
// speedup vs baseline: 1.3866x; 1.0237x over previous
#include <cuda_runtime.h>
#include <cuda_bf16.h>
#include <cstdint>

#define DEVFN __device__ __forceinline__

constexpr int TOKENS = 16 * 56 * 56;   // 50176
constexpr float SCALE = 0.17677669529663687f;   // 32^-0.5

// Scratch (static device arrays: allocation-free per harness rules)
__device__ float g_x2  [TOKENS * 256];
__device__ float g_btile[512 * 49 * 56];            // fused rel_bias+mask
__device__ __nv_bfloat16 g_q_bf [TOKENS * 256];     // (wb,h,n,d), pre-scaled
__device__ __nv_bfloat16 g_k_bf [TOKENS * 256];
__device__ __nv_bfloat16 g_v_bf [TOKENS * 256];
__device__ __nv_bfloat16 g_hw_bf [TOKENS * 256];    // LN1 out (windowed)
__device__ __nv_bfloat16 g_o_bf  [TOKENS * 256];    // attention out
__device__ __nv_bfloat16 g_h2n_bf[TOKENS * 256];    // LN2 out
__device__ __nv_bfloat16 g_mlp_bf[TOKENS * 1024];   // fc1+gelu out
__device__ __nv_bfloat16 g_wqkv_bf[768 * 256];
__device__ __nv_bfloat16 g_wprj_bf[256 * 256];
__device__ __nv_bfloat16 g_wfc1_bf[1024 * 256];
__device__ __nv_bfloat16 g_wfc2_bf[256 * 1024];

// ------------------------------ PTX helpers ---------------------------------
DEVFN uint32_t smem_u32(const void* p) {
    uint32_t a;
    asm("{ .reg .u64 t; cvta.to.shared.u64 t, %1; cvt.u32.u64 %0, t; }"
        : "=r"(a) : "l"(p));
    return a;
}
DEVFN uint32_t swz(uint32_t o) { return o ^ ((o >> 3) & 0x70u); }
DEVFN void cp16(uint32_t dst, const void* src) {
    asm volatile("cp.async.cg.shared.global [%0], [%1], 16;" :: "r"(dst), "l"(src));
}
DEVFN void mbar_init(uint32_t a, uint32_t c) {
    asm volatile("mbarrier.init.shared.b64 [%0], %1;" :: "r"(a), "r"(c) : "memory");
}
DEVFN void mbar_arrive(uint32_t a) {
    asm volatile("mbarrier.arrive.shared.b64 _, [%0];" :: "r"(a) : "memory");
}
DEVFN void cp_arrive(uint32_t a) {
    asm volatile("cp.async.mbarrier.arrive.noinc.shared.b64 [%0];" :: "r"(a) : "memory");
}
DEVFN void mbar_wait(uint32_t a, uint32_t par) {
    asm volatile(
        "{\n\t.reg .pred P;\n"
        "LAB_%=:\n\t"
        "mbarrier.try_wait.parity.acquire.cta.shared::cta.b64 P, [%0], %1, 0x989680;\n\t"
        "@!P bra LAB_%=;\n\t}"
        :: "r"(a), "r"(par) : "memory");
}
DEVFN uint32_t bfp(float a, float b) {   // pack 2 floats -> bf16x2 (RNE)
    __nv_bfloat162 t = __floats2bfloat162_rn(a, b);
    return *(uint32_t*)&t;
}
// bf16 mma: K=16 per instruction
DEVFN void mma16(float c[4], const uint32_t a[4], const uint32_t b0, const uint32_t b1) {
    asm volatile(
        "mma.sync.aligned.m16n8k16.row.col.f32.bf16.bf16.f32 "
        "{%0,%1,%2,%3}, {%4,%5,%6,%7}, {%8,%9}, {%0,%1,%2,%3};"
        : "+f"(c[0]), "+f"(c[1]), "+f"(c[2]), "+f"(c[3])
        : "r"(a[0]), "r"(a[1]), "r"(a[2]), "r"(a[3]), "r"(b0), "r"(b1));
}
DEVFN void ldsm4(uint32_t r[4], uint32_t addr) {
    asm volatile("ldmatrix.sync.aligned.m8n8.x4.shared.b16 {%0,%1,%2,%3}, [%4];"
        : "=r"(r[0]), "=r"(r[1]), "=r"(r[2]), "=r"(r[3]) : "r"(addr));
}
DEVFN void ldsm2(uint32_t r[2], uint32_t addr) {
    asm volatile("ldmatrix.sync.aligned.m8n8.x2.shared.b16 {%0,%1}, [%2];"
        : "=r"(r[0]), "=r"(r[1]) : "r"(addr));
}

// ---------------- fused prep: bias tiles (blocks 0-511) + weight cvt (512+) --
__global__ void __launch_bounds__(256) prep_all(
    const float* __restrict__ rel_bias, const float* __restrict__ mask,
    float* __restrict__ btile,
    const float4* __restrict__ w0, const float4* __restrict__ w1,
    const float4* __restrict__ w2, const float4* __restrict__ w3,
    uint2* __restrict__ d0, uint2* __restrict__ d1,
    uint2* __restrict__ d2, uint2* __restrict__ d3)
{
    int bid = blockIdx.x;
    if (bid < 512) {
        int h = bid >> 6;
        int widx = bid & 63;
        float* dst = btile + (size_t)bid * (49 * 56);
        const float* mrow = mask + (size_t)widx * 2401;
        for (int e = threadIdx.x; e < 49 * 56; e += 256) {
            int row = e / 56, col = e - row * 56;
            float v = -1e30f;
            if (col < 49) {
                int qi = row / 7, qj = row - qi * 7;
                int ki = col / 7, kj = col - ki * 7;
                int ridx = (qi - ki + 6) * 13 + (qj - kj + 6);
                v = rel_bias[ridx * 8 + h] + mrow[row * 49 + col];
            }
            dst[e] = v;
        }
    } else {
        int i = (bid - 512) * 256 + threadIdx.x;
        const float4* s; uint2* d; int j;
        if      (i <  49152) { s = w0; d = d0; j = i; }
        else if (i <  65536) { s = w1; d = d1; j = i - 49152; }
        else if (i < 131072) { s = w2; d = d2; j = i - 65536; }
        else                 { s = w3; d = d3; j = i - 131072; }
        float4 v = s[j];
        uint2 o; o.x = bfp(v.x, v.y); o.y = bfp(v.z, v.w);
        d[j] = o;
    }
}

// ---------------- LayerNorm (warp/row; bf16 output) --------------------------
__global__ void __launch_bounds__(256) ln_kernel(
    const float* __restrict__ in, __nv_bfloat16* __restrict__ out,
    const float* __restrict__ gamma, const float* __restrict__ beta,
    int shifted)
{
    int warp = threadIdx.x >> 5, lane = threadIdx.x & 31;
    int t = blockIdx.x * 8 + warp;
    int in_row, out_row;
    if (shifted) {
        int b = t / 3136; int rem = t - b * 3136;
        int i = rem / 56; int j = rem - i * 56;
        int si = i + 3; if (si >= 56) si -= 56;
        int sj = j + 3; if (sj >= 56) sj -= 56;
        in_row = b * 3136 + si * 56 + sj;
        int wb = b * 64 + (i / 7) * 8 + (j / 7);
        int n  = (i % 7) * 7 + (j % 7);
        out_row = wb * 49 + n;
    } else {
        in_row = out_row = t;
    }
    const float4* ip = (const float4*)(in + (size_t)in_row * 256);
    float4 a = ip[lane], b4 = ip[lane + 32];
    float s  = a.x + a.y + a.z + a.w + b4.x + b4.y + b4.z + b4.w;
    float sq = a.x*a.x + a.y*a.y + a.z*a.z + a.w*a.w
             + b4.x*b4.x + b4.y*b4.y + b4.z*b4.z + b4.w*b4.w;
    #pragma unroll
    for (int o = 16; o; o >>= 1) {
        s  += __shfl_xor_sync(0xffffffffu, s,  o);
        sq += __shfl_xor_sync(0xffffffffu, sq, o);
    }
    float mu   = s * (1.0f / 256.0f);
    float var  = sq * (1.0f / 256.0f) - mu * mu;
    float rstd = rsqrtf(var + 1e-5f);
    float4 g0 = ((const float4*)gamma)[lane], g1 = ((const float4*)gamma)[lane + 32];
    float4 e0 = ((const float4*)beta)[lane],  e1 = ((const float4*)beta)[lane + 32];
    uint2* op = (uint2*)(out + (size_t)out_row * 256);
    uint2 w0, w1;
    w0.x = bfp((a.x - mu) * rstd * g0.x + e0.x, (a.y - mu) * rstd * g0.y + e0.y);
    w0.y = bfp((a.z - mu) * rstd * g0.z + e0.z, (a.w - mu) * rstd * g0.w + e0.w);
    w1.x = bfp((b4.x - mu) * rstd * g1.x + e1.x, (b4.y - mu) * rstd * g1.y + e1.y);
    w1.y = bfp((b4.z - mu) * rstd * g1.z + e1.z, (b4.w - mu) * rstd * g1.w + e1.w);
    op[lane] = w0; op[lane + 32] = w1;
}

// ---------------- bf16 tensor-core windowed attention ------------------------
// One block per (window, head): 128 threads / 4 warps.
// qs/ks/vt/sc are bf16, 128B rows, GEMM-style swizzle; fragments via ldmatrix.
// QK^T: M=64(pad) x N=56(pad) x K=32. PV: M=64 x N=32 x K=64(pad, zeros).
// Scores/softmax fp32; P packed bf16; O bf16.
__global__ void __launch_bounds__(128, 6) attn_mma(const float* __restrict__ btile)
{
    int wb = blockIdx.x >> 3;
    int h  = blockIdx.x & 7;
    __shared__ __nv_bfloat16 smem[9728];   // 19456 B
    __nv_bfloat16* qs = smem;              // 64 rows x 64 bf16 (data in cols 0-31)
    __nv_bfloat16* ks = smem + 4096;       // 56 rows x 64
    __nv_bfloat16* vt = smem + 7680;       // 32 rows(dd) x 64 (keys; pads zeroed)
    __nv_bfloat16* sc = smem;              // P: 64 rows x 64, overlays qs

    const int t = threadIdx.x;
    const int l = t & 31, w = t >> 5;
    const int ra = l >> 2, ca = l & 3;
    const int mbase = w * 16;
    const size_t base = (size_t)blockIdx.x * (49 * 32);
    const float* bt = btile + (size_t)(h * 64 + (wb & 63)) * (49 * 56);

    const uint32_t qsB = smem_u32(qs), ksB = smem_u32(ks);
    const uint32_t vtB = smem_u32(vt), scB = smem_u32(sc);

    // phase 0: zero vt (256 uint4) + ks pad rows 49-55 (56 uint4)
    for (int idx = t; idx < 312; idx += 128) {
        if (idx < 256) ((uint4*)vt)[idx] = make_uint4(0, 0, 0, 0);
        else ((uint4*)ks)[392 + (idx - 256)] = make_uint4(0, 0, 0, 0);
    }
    __syncthreads();

    // phase 1: load q,k (16B chunks, swizzled) + v transposed
    for (int idx = t; idx < 392; idx += 128) {
        int j = idx; const __nv_bfloat16* src; __nv_bfloat16* dst;
        if (j < 196) { src = g_q_bf; dst = qs; }
        else         { src = g_k_bf; dst = ks; j -= 196; }
        int n = j >> 2, c = j & 3;
        uint4 val = *(const uint4*)(src + base + n * 32 + c * 8);
        *(uint4*)((char*)dst + n * 128 + ((c ^ (n & 7)) << 4)) = val;
    }
    // v transpose: 49 keys x 16 bf16-pairs (covers d = 0..31)   [R15 bug: was 392/&7]
    for (int idx = t; idx < 784; idx += 128) {
        int key = idx >> 4, dq = idx & 15;
        uint32_t pv = *(const uint32_t*)(g_v_bf + base + key * 32 + dq * 2);
        __nv_bfloat162 v2 = *(__nv_bfloat162*)&pv;
        int d0 = 2 * dq, d1 = 2 * dq + 1;
        vt[d0 * 64 + ((((key >> 1) ^ ((d0 & 7) << 2)) << 1) | (key & 1))] = v2.x;
        vt[d1 * 64 + ((((key >> 1) ^ ((d1 & 7) << 2)) << 1) | (key & 1))] = v2.y;
    }
    __syncthreads();

    const int r0 = mbase + ra, r1 = r0 + 8;
    const int r8 = l & 7, g8 = l >> 3;
    const uint32_t xw = (uint32_t)r8 << 2;
    const uint32_t aKC = (uint32_t)(g8 >> 1) * 4u;
    const uint32_t bKC = (uint32_t)(g8 & 1) * 4u;
    const uint32_t aRow = (uint32_t)(mbase + (g8 & 1) * 8 + r8) * 128u;

    // ---- QK^T (K=32: 2 k-steps) ----
    float acc[7][4];
    #pragma unroll
    for (int nt = 0; nt < 7; nt++)
        #pragma unroll
        for (int j = 0; j < 4; j++) acc[nt][j] = 0.f;

    #pragma unroll
    for (int kk = 0; kk < 2; kk++) {
        uint32_t af[4];
        ldsm4(af, qsB + aRow + (((uint32_t)kk * 8u + aKC) ^ xw) * 4u);
        uint32_t bOff = (((uint32_t)kk * 8u + bKC) ^ xw) * 4u;
        #pragma unroll
        for (int nt = 0; nt < 7; nt++) {
            uint32_t bf[2];
            ldsm2(bf, ksB + (uint32_t)(nt * 8 + r8) * 128u + bOff);
            mma16(acc[nt], af, bf[0], bf[1]);
        }
    }

    // ---- fused bias (-1e30 overwrites pad rows; pad cols via btile) ----
    #pragma unroll
    for (int nt = 0; nt < 7; nt++) {
        int cb = nt * 8 + 2 * ca;
        if (r0 < 49) {
            float2 b0 = *(const float2*)(bt + r0 * 56 + cb);
            acc[nt][0] += b0.x; acc[nt][1] += b0.y;
        } else { acc[nt][0] = -1e30f; acc[nt][1] = -1e30f; }
        if (r1 < 49) {
            float2 b1 = *(const float2*)(bt + r1 * 56 + cb);
            acc[nt][2] += b1.x; acc[nt][3] += b1.y;
        } else { acc[nt][2] = -1e30f; acc[nt][3] = -1e30f; }
    }

    // ---- register softmax (rows in 4-lane groups) ----
    float m0 = -1e30f, m1 = -1e30f;
    #pragma unroll
    for (int nt = 0; nt < 7; nt++) {
        m0 = fmaxf(m0, fmaxf(acc[nt][0], acc[nt][1]));
        m1 = fmaxf(m1, fmaxf(acc[nt][2], acc[nt][3]));
    }
    m0 = fmaxf(m0, __shfl_xor_sync(0xffffffffu, m0, 1));
    m0 = fmaxf(m0, __shfl_xor_sync(0xffffffffu, m0, 2));
    m1 = fmaxf(m1, __shfl_xor_sync(0xffffffffu, m1, 1));
    m1 = fmaxf(m1, __shfl_xor_sync(0xffffffffu, m1, 2));
    float s0 = 0.f, s1 = 0.f;
    #pragma unroll
    for (int nt = 0; nt < 7; nt++) {
        acc[nt][0] = __expf(acc[nt][0] - m0); s0 += acc[nt][0];
        acc[nt][1] = __expf(acc[nt][1] - m0); s0 += acc[nt][1];
        acc[nt][2] = __expf(acc[nt][2] - m1); s1 += acc[nt][2];
        acc[nt][3] = __expf(acc[nt][3] - m1); s1 += acc[nt][3];
    }
    s0 += __shfl_xor_sync(0xffffffffu, s0, 1);
    s0 += __shfl_xor_sync(0xffffffffu, s0, 2);
    s1 += __shfl_xor_sync(0xffffffffu, s1, 1);
    s1 += __shfl_xor_sync(0xffffffffu, s1, 2);
    float i0 = 1.0f / s0, i1 = 1.0f / s1;

    // ---- store normalized P as bf16 (overlays qs; own-warp rows only) ----
    const uint32_t x0w = (uint32_t)(r0 & 7) << 2;
    const uint32_t x1w = (uint32_t)(r1 & 7) << 2;
    #pragma unroll
    for (int nt = 0; nt < 7; nt++) {
        uint32_t wp = (uint32_t)(nt * 4 + ca);
        *(uint32_t*)((char*)sc + r0 * 128 + ((wp ^ x0w) << 2)) =
            bfp(acc[nt][0] * i0, acc[nt][1] * i0);
        *(uint32_t*)((char*)sc + r1 * 128 + ((wp ^ x1w) << 2)) =
            bfp(acc[nt][2] * i1, acc[nt][3] * i1);
    }
    {   // zero pad cols 56-63 (words 28-31)
        uint32_t wp = (uint32_t)(28 + ca);
        *(uint32_t*)((char*)sc + r0 * 128 + ((wp ^ x0w) << 2)) = 0u;
        *(uint32_t*)((char*)sc + r1 * 128 + ((wp ^ x1w) << 2)) = 0u;
    }
    __syncwarp();

    // ---- PV (K=64: 4 k-steps; pad keys are zero in both P and vt) ----
    float o[4][4];
    #pragma unroll
    for (int nt = 0; nt < 4; nt++)
        #pragma unroll
        for (int j = 0; j < 4; j++) o[nt][j] = 0.f;

    #pragma unroll
    for (int kk = 0; kk < 4; kk++) {
        uint32_t af[4];
        ldsm4(af, scB + aRow + (((uint32_t)kk * 8u + aKC) ^ xw) * 4u);
        uint32_t bOff = (((uint32_t)kk * 8u + bKC) ^ xw) * 4u;
        #pragma unroll
        for (int nt = 0; nt < 4; nt++) {
            uint32_t bf[2];
            ldsm2(bf, vtB + (uint32_t)(nt * 8 + r8) * 128u + bOff);
            mma16(o[nt], af, bf[0], bf[1]);
        }
    }

    // ---- store O as bf16 (feeds proj GEMM) ----
    #pragma unroll
    for (int half = 0; half < 2; half++) {
        int row = mbase + ra + half * 8;
        if (row < 49) {
            __nv_bfloat16* dst = g_o_bf + ((size_t)(wb * 49 + row)) * 256 + h * 32;
            #pragma unroll
            for (int nt = 0; nt < 4; nt++) {
                int col = nt * 8 + 2 * ca;
                *(uint32_t*)(dst + col) =
                    bfp(o[nt][half * 2 + 0], o[nt][half * 2 + 1]);
            }
        }
    }
}

// ---------------- bf16 mma.sync GEMM NT, 128x128 tile, K-chunk 64 ------------
// 3-stage pipeline with per-stage mbarriers (validated R14).
// MODE 0: QKV -> bf16 q(scaled)/k/v  MODE 1: proj+residual -> f32
// MODE 2: fc1+GELU -> bf16           MODE 3: fc2+residual -> f32
constexpr int GEMM_SMEM = 98304 + 64;

template <int MODE>
__global__ void __launch_bounds__(256, 2) mma_gemm(
    const __nv_bfloat16* __restrict__ A, const __nv_bfloat16* __restrict__ B,
    const float* __restrict__ bias, const float* __restrict__ res,
    float* __restrict__ O0, float* __restrict__ O1, float* __restrict__ O2,
    __nv_bfloat16* __restrict__ Ob, int K, int ldo)
{
    extern __shared__ float dsm[];
    const int t = threadIdx.x;
    const int rowBase = blockIdx.y * 128;
    const int colBase = blockIdx.x * 128;
    const uint32_t sbase = smem_u32(dsm);
    const uint32_t mb = sbase + 98304u;

    if (t == 0) {
        #pragma unroll
        for (int s2 = 0; s2 < 3; s2++) {
            mbar_init(mb + 8u * s2, 256);
            mbar_init(mb + 24u + 8u * s2, 256);
        }
    }
    __syncthreads();

    const int pr = t >> 1, ph = t & 1;
    const __nv_bfloat16* Ap = A + (size_t)(rowBase + pr) * K + ph * 32;
    const __nv_bfloat16* Bp = B + (size_t)(colBase + pr) * K + ph * 32;
    uint32_t poff[4];
    #pragma unroll
    for (int s = 0; s < 4; s++)
        poff[s] = swz((uint32_t)pr * 128u + (uint32_t)(ph * 4 + s) * 16u);

    const int T = K >> 6;
    #pragma unroll
    for (int p = 0; p < 2; p++) {
        uint32_t sA = sbase + (uint32_t)p * 32768u, sB = sA + 16384u;
        #pragma unroll
        for (int s = 0; s < 4; s++) {
            cp16(sA + poff[s], Ap + p * 64 + s * 8);
            cp16(sB + poff[s], Bp + p * 64 + s * 8);
        }
        cp_arrive(mb + 8u * (uint32_t)p);
    }

    const int l = t & 31, w = t >> 5;
    const int wr = w >> 2, wc = w & 3;
    const int ra = l >> 2, ca = l & 3;

    const int r8 = l & 7, g8 = l >> 3;
    const uint32_t xw = (uint32_t)r8 << 2;
    const uint32_t aKC = (uint32_t)(g8 >> 1) * 4u;
    const uint32_t bKC = (uint32_t)(g8 & 1) * 4u;
    uint32_t aRow[4], bRow[4];
    #pragma unroll
    for (int mt = 0; mt < 4; mt++)
        aRow[mt] = (uint32_t)(wr * 64 + mt * 16 + (g8 & 1) * 8 + r8) * 128u;
    #pragma unroll
    for (int nt = 0; nt < 4; nt++)
        bRow[nt] = (uint32_t)(wc * 32 + nt * 8 + r8) * 128u;

    float c[4][4][4];
    #pragma unroll
    for (int mt = 0; mt < 4; mt++)
        #pragma unroll
        for (int nt = 0; nt < 4; nt++)
            #pragma unroll
            for (int j = 0; j < 4; j++) c[mt][nt][j] = 0.f;

    int r = 0, qd = 0;          // i = 3*qd + r
    for (int i = 0; i < T; i++) {
        mbar_wait(mb + 8u * (uint32_t)r, (uint32_t)(qd & 1));

        if (i + 2 < T) {
            int ws = (r == 0) ? 2 : r - 1;
            if (i >= 1) {
                int pfree = ((r >= 1) ? qd : qd - 1) & 1;
                mbar_wait(mb + 24u + 8u * (uint32_t)ws, (uint32_t)pfree);
            }
            uint32_t sA = sbase + (uint32_t)ws * 32768u, sB = sA + 16384u;
            #pragma unroll
            for (int s = 0; s < 4; s++) {
                cp16(sA + poff[s], Ap + (i + 2) * 64 + s * 8);
                cp16(sB + poff[s], Bp + (i + 2) * 64 + s * 8);
            }
            cp_arrive(mb + 8u * (uint32_t)ws);
        }

        const uint32_t AsB = sbase + (uint32_t)r * 32768u;
        const uint32_t BsB = AsB + 16384u;
        #pragma unroll
        for (int kk = 0; kk < 4; kk++) {
            const uint32_t aOff = (((uint32_t)kk * 8u + aKC) ^ xw) * 4u;
            const uint32_t bOff = (((uint32_t)kk * 8u + bKC) ^ xw) * 4u;
            uint32_t af[4][4], bf[4][2];
            #pragma unroll
            for (int mt = 0; mt < 4; mt++)
                ldsm4(af[mt], AsB + aRow[mt] + aOff);
            #pragma unroll
            for (int nt = 0; nt < 4; nt++)
                ldsm2(bf[nt], BsB + bRow[nt] + bOff);
            #pragma unroll
            for (int mt = 0; mt < 4; mt++)
                #pragma unroll
                for (int nt = 0; nt < 4; nt++)
                    mma16(c[mt][nt], af[mt], bf[nt][0], bf[nt][1]);
        }
        mbar_arrive(mb + 24u + 8u * (uint32_t)r);

        if (++r == 3) { r = 0; qd++; }
    }

    // ---------------- epilogue ----------------
    #pragma unroll
    for (int mt = 0; mt < 4; mt++) {
        #pragma unroll
        for (int rr = 0; rr < 2; rr++) {
            const int gm = rowBase + wr * 64 + mt * 16 + ra + rr * 8;
            int wb = 0, n = 0; size_t orow = 0;
            if (MODE == 0) { wb = gm / 49; n = gm - wb * 49; }
            if (MODE == 1) {
                wb = gm / 49; n = gm - wb * 49;
                int b = wb >> 6; int widx = wb & 63;
                int ii = (widx >> 3) * 7 + n / 7;
                int jj = (widx & 7) * 7 + n % 7;
                int oi = ii + 3; if (oi >= 56) oi -= 56;
                int oj = jj + 3; if (oj >= 56) oj -= 56;
                orow = ((size_t)b * 3136 + oi * 56 + oj) * 256;
            }
            if (MODE == 2 || MODE == 3) orow = (size_t)gm * ldo;

            #pragma unroll
            for (int nt = 0; nt < 4; nt++) {
                const int gc = colBase + wc * 32 + nt * 8 + 2 * ca;
                float2 bb = *(const float2*)(bias + gc);
                float v0 = c[mt][nt][rr * 2 + 0] + bb.x;
                float v1 = c[mt][nt][rr * 2 + 1] + bb.y;

                if (MODE == 0) {
                    int part = gc >> 8;
                    int hh = (gc >> 5) & 7;
                    int dd = gc & 31;
                    __nv_bfloat16* Op = (__nv_bfloat16*)((part == 0) ? O0 : ((part == 1) ? O1 : O2));
                    if (part == 0) { v0 *= SCALE; v1 *= SCALE; }
                    *(uint32_t*)(Op + (((size_t)wb * 8 + hh) * 49 + n) * 32 + dd)
                        = bfp(v0, v1);
                } else if (MODE == 1) {
                    float2 rr2 = *(const float2*)(res + orow + gc);
                    *(float2*)(O0 + orow + gc) = make_float2(rr2.x + v0, rr2.y + v1);
                } else if (MODE == 2) {
                    v0 = 0.5f * v0 * (1.0f + erff(v0 * 0.70710678118654752f));
                    v1 = 0.5f * v1 * (1.0f + erff(v1 * 0.70710678118654752f));
                    *(uint32_t*)(Ob + orow + gc) = bfp(v0, v1);
                } else {
                    float2 rr2 = *(const float2*)(res + orow + gc);
                    *(float2*)(O0 + orow + gc) = make_float2(rr2.x + v0, rr2.y + v1);
                }
            }
        }
    }
}

// ----------------------------------------------------------------------------
extern "C" void kernel_launch(void* const* d_in, const int* in_sizes, int n_in,
                              void* d_out, int out_size)
{
    const float* x      = (const float*)d_in[0];
    const float* mask   = (const float*)d_in[1];
    const float* n1g    = (const float*)d_in[2];
    const float* n1b    = (const float*)d_in[3];
    const float* qkv_w  = (const float*)d_in[4];
    const float* qkv_b  = (const float*)d_in[5];
    const float* relb   = (const float*)d_in[6];
    const float* proj_w = (const float*)d_in[7];
    const float* proj_b = (const float*)d_in[8];
    const float* n2g    = (const float*)d_in[9];
    const float* n2b    = (const float*)d_in[10];
    const float* fc1_w  = (const float*)d_in[11];
    const float* fc1_b  = (const float*)d_in[12];
    const float* fc2_w  = (const float*)d_in[13];
    const float* fc2_b  = (const float*)d_in[14];
    float* out = (float*)d_out;

    float *p_x2, *p_btile;
    __nv_bfloat16 *p_q, *p_k, *p_v;
    __nv_bfloat16 *p_hw, *p_o, *p_h2n, *p_mlp;
    __nv_bfloat16 *p_wqkv, *p_wprj, *p_wfc1, *p_wfc2;
    cudaGetSymbolAddress((void**)&p_x2,    g_x2);
    cudaGetSymbolAddress((void**)&p_btile, g_btile);
    cudaGetSymbolAddress((void**)&p_q,     g_q_bf);
    cudaGetSymbolAddress((void**)&p_k,     g_k_bf);
    cudaGetSymbolAddress((void**)&p_v,     g_v_bf);
    cudaGetSymbolAddress((void**)&p_hw,    g_hw_bf);
    cudaGetSymbolAddress((void**)&p_o,     g_o_bf);
    cudaGetSymbolAddress((void**)&p_h2n,   g_h2n_bf);
    cudaGetSymbolAddress((void**)&p_mlp,   g_mlp_bf);
    cudaGetSymbolAddress((void**)&p_wqkv,  g_wqkv_bf);
    cudaGetSymbolAddress((void**)&p_wprj,  g_wprj_bf);
    cudaGetSymbolAddress((void**)&p_wfc1,  g_wfc1_bf);
    cudaGetSymbolAddress((void**)&p_wfc2,  g_wfc2_bf);

    cudaFuncSetAttribute(mma_gemm<0>, cudaFuncAttributeMaxDynamicSharedMemorySize, GEMM_SMEM);
    cudaFuncSetAttribute(mma_gemm<1>, cudaFuncAttributeMaxDynamicSharedMemorySize, GEMM_SMEM);
    cudaFuncSetAttribute(mma_gemm<2>, cudaFuncAttributeMaxDynamicSharedMemorySize, GEMM_SMEM);
    cudaFuncSetAttribute(mma_gemm<3>, cudaFuncAttributeMaxDynamicSharedMemorySize, GEMM_SMEM);

    // 0. fused prep: bias tiles + weight bf16 conversion
    prep_all<<<1280, 256>>>(relb, mask, p_btile,
                            (const float4*)qkv_w, (const float4*)proj_w,
                            (const float4*)fc1_w, (const float4*)fc2_w,
                            (uint2*)p_wqkv, (uint2*)p_wprj,
                            (uint2*)p_wfc1, (uint2*)p_wfc2);
    // 1. LN1 + shift + window partition -> bf16
    ln_kernel<<<TOKENS / 8, 256>>>(x, p_hw, n1g, n1b, 1);
    // 2. QKV (bf16 mma) -> q(scaled)/k/v bf16 in (wb,h,n,d)
    mma_gemm<0><<<dim3(6, 392), 256, GEMM_SMEM>>>(p_hw, p_wqkv, qkv_b, nullptr,
                                                  (float*)p_q, (float*)p_k, (float*)p_v,
                                                  nullptr, 256, 0);
    // 3. Windowed MSA (bf16 tensor-core, ldmatrix) -> bf16
    attn_mma<<<8192, 128>>>(p_btile);
    // 4. proj (bf16 mma) + window-reverse + un-roll + residual(x) -> f32
    mma_gemm<1><<<dim3(2, 392), 256, GEMM_SMEM>>>(p_o, p_wprj, proj_b, x,
                                                  p_x2, nullptr, nullptr, nullptr, 256, 256);
    // 5. LN2 -> bf16
    ln_kernel<<<TOKENS / 8, 256>>>(p_x2, p_h2n, n2g, n2b, 0);
    // 6. fc1 (bf16 mma) + GELU -> bf16
    mma_gemm<2><<<dim3(8, 392), 256, GEMM_SMEM>>>(p_h2n, p_wfc1, fc1_b, nullptr,
                                                  nullptr, nullptr, nullptr, p_mlp, 256, 1024);
    // 7. fc2 (bf16 mma) + residual(x2) -> out
    mma_gemm<3><<<dim3(2, 392), 256, GEMM_SMEM>>>(p_mlp, p_wfc2, fc2_b, p_x2,
                                                  out, nullptr, nullptr, nullptr, 1024, 256);
}

// round 17
// speedup vs baseline: 1.4375x; 1.0367x over previous
#include <cuda_runtime.h>
#include <cuda_bf16.h>
#include <cstdint>

#define DEVFN __device__ __forceinline__

constexpr int TOKENS = 16 * 56 * 56;   // 50176
constexpr float SCALE = 0.17677669529663687f;   // 32^-0.5

// Scratch (static device arrays: allocation-free per harness rules)
__device__ float g_x2  [TOKENS * 256];
__device__ float g_btile[512 * 49 * 56];            // fused rel_bias+mask
__device__ __nv_bfloat16 g_q_bf [TOKENS * 256];     // (wb,h,n,d), pre-scaled
__device__ __nv_bfloat16 g_k_bf [TOKENS * 256];
__device__ __nv_bfloat16 g_v_bf [TOKENS * 256];
__device__ __nv_bfloat16 g_hw_bf [TOKENS * 256];    // LN1 out (windowed)
__device__ __nv_bfloat16 g_o_bf  [TOKENS * 256];    // attention out
__device__ __nv_bfloat16 g_h2n_bf[TOKENS * 256];    // LN2 out
__device__ __nv_bfloat16 g_mlp_bf[TOKENS * 1024];   // fc1+gelu out
__device__ __nv_bfloat16 g_wqkv_bf[768 * 256];
__device__ __nv_bfloat16 g_wprj_bf[256 * 256];
__device__ __nv_bfloat16 g_wfc1_bf[1024 * 256];
__device__ __nv_bfloat16 g_wfc2_bf[256 * 1024];

// ------------------------------ PTX helpers ---------------------------------
DEVFN uint32_t smem_u32(const void* p) {
    uint32_t a;
    asm("{ .reg .u64 t; cvta.to.shared.u64 t, %1; cvt.u32.u64 %0, t; }"
        : "=r"(a) : "l"(p));
    return a;
}
DEVFN uint32_t swz(uint32_t o) { return o ^ ((o >> 3) & 0x70u); }
DEVFN void cp16(uint32_t dst, const void* src) {
    asm volatile("cp.async.cg.shared.global [%0], [%1], 16;" :: "r"(dst), "l"(src));
}
DEVFN void mbar_init(uint32_t a, uint32_t c) {
    asm volatile("mbarrier.init.shared.b64 [%0], %1;" :: "r"(a), "r"(c) : "memory");
}
DEVFN void mbar_arrive(uint32_t a) {
    asm volatile("mbarrier.arrive.shared.b64 _, [%0];" :: "r"(a) : "memory");
}
DEVFN void cp_arrive(uint32_t a) {
    asm volatile("cp.async.mbarrier.arrive.noinc.shared.b64 [%0];" :: "r"(a) : "memory");
}
DEVFN void mbar_wait(uint32_t a, uint32_t par) {
    asm volatile(
        "{\n\t.reg .pred P;\n"
        "LAB_%=:\n\t"
        "mbarrier.try_wait.parity.acquire.cta.shared::cta.b64 P, [%0], %1, 0x989680;\n\t"
        "@!P bra LAB_%=;\n\t}"
        :: "r"(a), "r"(par) : "memory");
}
DEVFN uint32_t bfp(float a, float b) {   // pack 2 floats -> bf16x2 (RNE)
    __nv_bfloat162 t = __floats2bfloat162_rn(a, b);
    return *(uint32_t*)&t;
}
// bf16 mma: K=16 per instruction
DEVFN void mma16(float c[4], const uint32_t a[4], const uint32_t b0, const uint32_t b1) {
    asm volatile(
        "mma.sync.aligned.m16n8k16.row.col.f32.bf16.bf16.f32 "
        "{%0,%1,%2,%3}, {%4,%5,%6,%7}, {%8,%9}, {%0,%1,%2,%3};"
        : "+f"(c[0]), "+f"(c[1]), "+f"(c[2]), "+f"(c[3])
        : "r"(a[0]), "r"(a[1]), "r"(a[2]), "r"(a[3]), "r"(b0), "r"(b1));
}
DEVFN void ldsm4(uint32_t r[4], uint32_t addr) {
    asm volatile("ldmatrix.sync.aligned.m8n8.x4.shared.b16 {%0,%1,%2,%3}, [%4];"
        : "=r"(r[0]), "=r"(r[1]), "=r"(r[2]), "=r"(r[3]) : "r"(addr));
}
DEVFN void ldsm4t(uint32_t r[4], uint32_t addr) {
    asm volatile("ldmatrix.sync.aligned.m8n8.x4.trans.shared.b16 {%0,%1,%2,%3}, [%4];"
        : "=r"(r[0]), "=r"(r[1]), "=r"(r[2]), "=r"(r[3]) : "r"(addr));
}
DEVFN void ldsm2(uint32_t r[2], uint32_t addr) {
    asm volatile("ldmatrix.sync.aligned.m8n8.x2.shared.b16 {%0,%1}, [%2];"
        : "=r"(r[0]), "=r"(r[1]) : "r"(addr));
}

// ---------------- fused prep: bias tiles (blocks 0-511) + weight cvt (512+) --
__global__ void __launch_bounds__(256) prep_all(
    const float* __restrict__ rel_bias, const float* __restrict__ mask,
    float* __restrict__ btile,
    const float4* __restrict__ w0, const float4* __restrict__ w1,
    const float4* __restrict__ w2, const float4* __restrict__ w3,
    uint2* __restrict__ d0, uint2* __restrict__ d1,
    uint2* __restrict__ d2, uint2* __restrict__ d3)
{
    int bid = blockIdx.x;
    if (bid < 512) {
        int h = bid >> 6;
        int widx = bid & 63;
        float* dst = btile + (size_t)bid * (49 * 56);
        const float* mrow = mask + (size_t)widx * 2401;
        for (int e = threadIdx.x; e < 49 * 56; e += 256) {
            int row = e / 56, col = e - row * 56;
            float v = -1e30f;
            if (col < 49) {
                int qi = row / 7, qj = row - qi * 7;
                int ki = col / 7, kj = col - ki * 7;
                int ridx = (qi - ki + 6) * 13 + (qj - kj + 6);
                v = rel_bias[ridx * 8 + h] + mrow[row * 49 + col];
            }
            dst[e] = v;
        }
    } else {
        int i = (bid - 512) * 256 + threadIdx.x;
        const float4* s; uint2* d; int j;
        if      (i <  49152) { s = w0; d = d0; j = i; }
        else if (i <  65536) { s = w1; d = d1; j = i - 49152; }
        else if (i < 131072) { s = w2; d = d2; j = i - 65536; }
        else                 { s = w3; d = d3; j = i - 131072; }
        float4 v = s[j];
        uint2 o; o.x = bfp(v.x, v.y); o.y = bfp(v.z, v.w);
        d[j] = o;
    }
}

// ---------------- LayerNorm (warp/row; bf16 output) --------------------------
__global__ void __launch_bounds__(256) ln_kernel(
    const float* __restrict__ in, __nv_bfloat16* __restrict__ out,
    const float* __restrict__ gamma, const float* __restrict__ beta,
    int shifted)
{
    int warp = threadIdx.x >> 5, lane = threadIdx.x & 31;
    int t = blockIdx.x * 8 + warp;
    int in_row, out_row;
    if (shifted) {
        int b = t / 3136; int rem = t - b * 3136;
        int i = rem / 56; int j = rem - i * 56;
        int si = i + 3; if (si >= 56) si -= 56;
        int sj = j + 3; if (sj >= 56) sj -= 56;
        in_row = b * 3136 + si * 56 + sj;
        int wb = b * 64 + (i / 7) * 8 + (j / 7);
        int n  = (i % 7) * 7 + (j % 7);
        out_row = wb * 49 + n;
    } else {
        in_row = out_row = t;
    }
    const float4* ip = (const float4*)(in + (size_t)in_row * 256);
    float4 a = ip[lane], b4 = ip[lane + 32];
    float s  = a.x + a.y + a.z + a.w + b4.x + b4.y + b4.z + b4.w;
    float sq = a.x*a.x + a.y*a.y + a.z*a.z + a.w*a.w
             + b4.x*b4.x + b4.y*b4.y + b4.z*b4.z + b4.w*b4.w;
    #pragma unroll
    for (int o = 16; o; o >>= 1) {
        s  += __shfl_xor_sync(0xffffffffu, s,  o);
        sq += __shfl_xor_sync(0xffffffffu, sq, o);
    }
    float mu   = s * (1.0f / 256.0f);
    float var  = sq * (1.0f / 256.0f) - mu * mu;
    float rstd = rsqrtf(var + 1e-5f);
    float4 g0 = ((const float4*)gamma)[lane], g1 = ((const float4*)gamma)[lane + 32];
    float4 e0 = ((const float4*)beta)[lane],  e1 = ((const float4*)beta)[lane + 32];
    uint2* op = (uint2*)(out + (size_t)out_row * 256);
    uint2 w0, w1;
    w0.x = bfp((a.x - mu) * rstd * g0.x + e0.x, (a.y - mu) * rstd * g0.y + e0.y);
    w0.y = bfp((a.z - mu) * rstd * g0.z + e0.z, (a.w - mu) * rstd * g0.w + e0.w);
    w1.x = bfp((b4.x - mu) * rstd * g1.x + e1.x, (b4.y - mu) * rstd * g1.y + e1.y);
    w1.y = bfp((b4.z - mu) * rstd * g1.z + e1.z, (b4.w - mu) * rstd * g1.w + e1.w);
    op[lane] = w0; op[lane + 32] = w1;
}

// ---------------- bf16 tensor-core windowed attention ------------------------
// One block per (window, head): 128 threads / 4 warps.
// qs/ks/vs all key/query-major (rows x 128B swizzled); V B-fragments come from
// ldmatrix.x4.TRANS (no smem transpose). Scores/softmax fp32; P bf16; O bf16.
__global__ void __launch_bounds__(128, 6) attn_mma(const float* __restrict__ btile)
{
    int wb = blockIdx.x >> 3;
    int h  = blockIdx.x & 7;
    __shared__ __nv_bfloat16 smem[11776];  // 23552 B
    __nv_bfloat16* qs = smem;              // 64 rows x 64 bf16 (data cols 0-31)
    __nv_bfloat16* ks = smem + 4096;       // 56 rows x 64
    __nv_bfloat16* vs = smem + 7680;       // 64 rows(keys) x 64 (pad rows zeroed)
    __nv_bfloat16* sc = smem;              // P: 64 rows x 64, overlays qs

    const int t = threadIdx.x;
    const int l = t & 31, w = t >> 5;
    const int ra = l >> 2, ca = l & 3;
    const int mbase = w * 16;
    const size_t base = (size_t)blockIdx.x * (49 * 32);
    const float* bt = btile + (size_t)(h * 64 + (wb & 63)) * (49 * 56);

    const uint32_t qsB = smem_u32(qs), ksB = smem_u32(ks);
    const uint32_t vsB = smem_u32(vs), scB = smem_u32(sc);

    // single load phase: q/k/v 16B swizzled copies + pad zeroing (disjoint rows)
    for (int idx = t; idx < 588; idx += 128) {
        int j = idx; const __nv_bfloat16* src; __nv_bfloat16* dst;
        if (j < 196)      { src = g_q_bf; dst = qs; }
        else if (j < 392) { src = g_k_bf; dst = ks; j -= 196; }
        else              { src = g_v_bf; dst = vs; j -= 392; }
        int n = j >> 2, c = j & 3;
        uint4 val = *(const uint4*)(src + base + n * 32 + c * 8);
        *(uint4*)((char*)dst + n * 128 + ((c ^ (n & 7)) << 4)) = val;
    }
    // zero: ks rows 49-55 (56 uint4) + vs rows 49-63 (120 uint4)
    for (int idx = t; idx < 176; idx += 128) {
        if (idx < 56) ((uint4*)ks)[392 + idx] = make_uint4(0, 0, 0, 0);
        else ((uint4*)vs)[392 + (idx - 56)] = make_uint4(0, 0, 0, 0);
    }
    __syncthreads();

    const int r0 = mbase + ra, r1 = r0 + 8;
    const int r8 = l & 7, g8 = l >> 3;
    const uint32_t xw = (uint32_t)r8 << 2;
    const uint32_t aKC = (uint32_t)(g8 >> 1) * 4u;
    const uint32_t bKC = (uint32_t)(g8 & 1) * 4u;
    const uint32_t aRow = (uint32_t)(mbase + (g8 & 1) * 8 + r8) * 128u;

    // ---- QK^T (K=32: 2 k-steps) ----
    float acc[7][4];
    #pragma unroll
    for (int nt = 0; nt < 7; nt++)
        #pragma unroll
        for (int j = 0; j < 4; j++) acc[nt][j] = 0.f;

    #pragma unroll
    for (int kk = 0; kk < 2; kk++) {
        uint32_t af[4];
        ldsm4(af, qsB + aRow + (((uint32_t)kk * 8u + aKC) ^ xw) * 4u);
        uint32_t bOff = (((uint32_t)kk * 8u + bKC) ^ xw) * 4u;
        #pragma unroll
        for (int nt = 0; nt < 7; nt++) {
            uint32_t bf[2];
            ldsm2(bf, ksB + (uint32_t)(nt * 8 + r8) * 128u + bOff);
            mma16(acc[nt], af, bf[0], bf[1]);
        }
    }

    // ---- fused bias (-1e30 overwrites pad rows; pad cols via btile) ----
    #pragma unroll
    for (int nt = 0; nt < 7; nt++) {
        int cb = nt * 8 + 2 * ca;
        if (r0 < 49) {
            float2 b0 = *(const float2*)(bt + r0 * 56 + cb);
            acc[nt][0] += b0.x; acc[nt][1] += b0.y;
        } else { acc[nt][0] = -1e30f; acc[nt][1] = -1e30f; }
        if (r1 < 49) {
            float2 b1 = *(const float2*)(bt + r1 * 56 + cb);
            acc[nt][2] += b1.x; acc[nt][3] += b1.y;
        } else { acc[nt][2] = -1e30f; acc[nt][3] = -1e30f; }
    }

    // ---- register softmax (rows in 4-lane groups) ----
    float m0 = -1e30f, m1 = -1e30f;
    #pragma unroll
    for (int nt = 0; nt < 7; nt++) {
        m0 = fmaxf(m0, fmaxf(acc[nt][0], acc[nt][1]));
        m1 = fmaxf(m1, fmaxf(acc[nt][2], acc[nt][3]));
    }
    m0 = fmaxf(m0, __shfl_xor_sync(0xffffffffu, m0, 1));
    m0 = fmaxf(m0, __shfl_xor_sync(0xffffffffu, m0, 2));
    m1 = fmaxf(m1, __shfl_xor_sync(0xffffffffu, m1, 1));
    m1 = fmaxf(m1, __shfl_xor_sync(0xffffffffu, m1, 2));
    float s0 = 0.f, s1 = 0.f;
    #pragma unroll
    for (int nt = 0; nt < 7; nt++) {
        acc[nt][0] = __expf(acc[nt][0] - m0); s0 += acc[nt][0];
        acc[nt][1] = __expf(acc[nt][1] - m0); s0 += acc[nt][1];
        acc[nt][2] = __expf(acc[nt][2] - m1); s1 += acc[nt][2];
        acc[nt][3] = __expf(acc[nt][3] - m1); s1 += acc[nt][3];
    }
    s0 += __shfl_xor_sync(0xffffffffu, s0, 1);
    s0 += __shfl_xor_sync(0xffffffffu, s0, 2);
    s1 += __shfl_xor_sync(0xffffffffu, s1, 1);
    s1 += __shfl_xor_sync(0xffffffffu, s1, 2);
    float i0 = 1.0f / s0, i1 = 1.0f / s1;

    // ---- store normalized P as bf16 (overlays qs; own-warp rows only) ----
    const uint32_t x0w = (uint32_t)(r0 & 7) << 2;
    const uint32_t x1w = (uint32_t)(r1 & 7) << 2;
    #pragma unroll
    for (int nt = 0; nt < 7; nt++) {
        uint32_t wp = (uint32_t)(nt * 4 + ca);
        *(uint32_t*)((char*)sc + r0 * 128 + ((wp ^ x0w) << 2)) =
            bfp(acc[nt][0] * i0, acc[nt][1] * i0);
        *(uint32_t*)((char*)sc + r1 * 128 + ((wp ^ x1w) << 2)) =
            bfp(acc[nt][2] * i1, acc[nt][3] * i1);
    }
    {   // zero pad cols 56-63 (words 28-31)
        uint32_t wp = (uint32_t)(28 + ca);
        *(uint32_t*)((char*)sc + r0 * 128 + ((wp ^ x0w) << 2)) = 0u;
        *(uint32_t*)((char*)sc + r1 * 128 + ((wp ^ x1w) << 2)) = 0u;
    }
    __syncwarp();

    // ---- PV (K=64: 4 k-steps; B-fragments via ldmatrix.trans of vs) ----
    // lane addr: row = kk*16 + (l&15); chunk = 2*cb + (l>>4); swizzle per row.
    const int rowl = l & 15;
    const uint32_t vbase = vsB + (uint32_t)rowl * 128u;
    const uint32_t cv0 = (uint32_t)((0 + (l >> 4)) ^ (rowl & 7)) << 4;  // cb=0
    const uint32_t cv1 = (uint32_t)((2 + (l >> 4)) ^ (rowl & 7)) << 4;  // cb=1

    float o[4][4];
    #pragma unroll
    for (int nt = 0; nt < 4; nt++)
        #pragma unroll
        for (int j = 0; j < 4; j++) o[nt][j] = 0.f;

    #pragma unroll
    for (int kk = 0; kk < 4; kk++) {
        uint32_t af[4];
        ldsm4(af, scB + aRow + (((uint32_t)kk * 8u + aKC) ^ xw) * 4u);
        uint32_t vrow = vbase + (uint32_t)kk * 2048u;   // kk*16 rows * 128B
        uint32_t bt0[4], bt1[4];
        ldsm4t(bt0, vrow + cv0);   // m0/m1: keys kk*16+0..15 @ dims 0-7  -> nt0
                                   // m2/m3: same keys       @ dims 8-15 -> nt1
        ldsm4t(bt1, vrow + cv1);   // dims 16-23 -> nt2, 24-31 -> nt3
        mma16(o[0], af, bt0[0], bt0[1]);
        mma16(o[1], af, bt0[2], bt0[3]);
        mma16(o[2], af, bt1[0], bt1[1]);
        mma16(o[3], af, bt1[2], bt1[3]);
    }

    // ---- store O as bf16 (feeds proj GEMM) ----
    #pragma unroll
    for (int half = 0; half < 2; half++) {
        int row = mbase + ra + half * 8;
        if (row < 49) {
            __nv_bfloat16* dst = g_o_bf + ((size_t)(wb * 49 + row)) * 256 + h * 32;
            #pragma unroll
            for (int nt = 0; nt < 4; nt++) {
                int col = nt * 8 + 2 * ca;
                *(uint32_t*)(dst + col) =
                    bfp(o[nt][half * 2 + 0], o[nt][half * 2 + 1]);
            }
        }
    }
}

// ---------------- bf16 mma.sync GEMM NT, 128x128 tile, K-chunk 64 ------------
// 3-stage pipeline with per-stage mbarriers (validated R14).
// MODE 0: QKV -> bf16 q(scaled)/k/v  MODE 1: proj+residual -> f32
// MODE 2: fc1+GELU -> bf16           MODE 3: fc2+residual -> f32
constexpr int GEMM_SMEM = 98304 + 64;

template <int MODE>
__global__ void __launch_bounds__(256, 2) mma_gemm(
    const __nv_bfloat16* __restrict__ A, const __nv_bfloat16* __restrict__ B,
    const float* __restrict__ bias, const float* __restrict__ res,
    float* __restrict__ O0, float* __restrict__ O1, float* __restrict__ O2,
    __nv_bfloat16* __restrict__ Ob, int K, int ldo)
{
    extern __shared__ float dsm[];
    const int t = threadIdx.x;
    const int rowBase = blockIdx.y * 128;
    const int colBase = blockIdx.x * 128;
    const uint32_t sbase = smem_u32(dsm);
    const uint32_t mb = sbase + 98304u;

    if (t == 0) {
        #pragma unroll
        for (int s2 = 0; s2 < 3; s2++) {
            mbar_init(mb + 8u * s2, 256);
            mbar_init(mb + 24u + 8u * s2, 256);
        }
    }
    __syncthreads();

    const int pr = t >> 1, ph = t & 1;
    const __nv_bfloat16* Ap = A + (size_t)(rowBase + pr) * K + ph * 32;
    const __nv_bfloat16* Bp = B + (size_t)(colBase + pr) * K + ph * 32;
    uint32_t poff[4];
    #pragma unroll
    for (int s = 0; s < 4; s++)
        poff[s] = swz((uint32_t)pr * 128u + (uint32_t)(ph * 4 + s) * 16u);

    const int T = K >> 6;
    #pragma unroll
    for (int p = 0; p < 2; p++) {
        uint32_t sA = sbase + (uint32_t)p * 32768u, sB = sA + 16384u;
        #pragma unroll
        for (int s = 0; s < 4; s++) {
            cp16(sA + poff[s], Ap + p * 64 + s * 8);
            cp16(sB + poff[s], Bp + p * 64 + s * 8);
        }
        cp_arrive(mb + 8u * (uint32_t)p);
    }

    const int l = t & 31, w = t >> 5;
    const int wr = w >> 2, wc = w & 3;
    const int ra = l >> 2, ca = l & 3;

    const int r8 = l & 7, g8 = l >> 3;
    const uint32_t xw = (uint32_t)r8 << 2;
    const uint32_t aKC = (uint32_t)(g8 >> 1) * 4u;
    const uint32_t bKC = (uint32_t)(g8 & 1) * 4u;
    uint32_t aRow[4], bRow[4];
    #pragma unroll
    for (int mt = 0; mt < 4; mt++)
        aRow[mt] = (uint32_t)(wr * 64 + mt * 16 + (g8 & 1) * 8 + r8) * 128u;
    #pragma unroll
    for (int nt = 0; nt < 4; nt++)
        bRow[nt] = (uint32_t)(wc * 32 + nt * 8 + r8) * 128u;

    float c[4][4][4];
    #pragma unroll
    for (int mt = 0; mt < 4; mt++)
        #pragma unroll
        for (int nt = 0; nt < 4; nt++)
            #pragma unroll
            for (int j = 0; j < 4; j++) c[mt][nt][j] = 0.f;

    int r = 0, qd = 0;          // i = 3*qd + r
    for (int i = 0; i < T; i++) {
        mbar_wait(mb + 8u * (uint32_t)r, (uint32_t)(qd & 1));

        if (i + 2 < T) {
            int ws = (r == 0) ? 2 : r - 1;
            if (i >= 1) {
                int pfree = ((r >= 1) ? qd : qd - 1) & 1;
                mbar_wait(mb + 24u + 8u * (uint32_t)ws, (uint32_t)pfree);
            }
            uint32_t sA = sbase + (uint32_t)ws * 32768u, sB = sA + 16384u;
            #pragma unroll
            for (int s = 0; s < 4; s++) {
                cp16(sA + poff[s], Ap + (i + 2) * 64 + s * 8);
                cp16(sB + poff[s], Bp + (i + 2) * 64 + s * 8);
            }
            cp_arrive(mb + 8u * (uint32_t)ws);
        }

        const uint32_t AsB = sbase + (uint32_t)r * 32768u;
        const uint32_t BsB = AsB + 16384u;
        #pragma unroll
        for (int kk = 0; kk < 4; kk++) {
            const uint32_t aOff = (((uint32_t)kk * 8u + aKC) ^ xw) * 4u;
            const uint32_t bOff = (((uint32_t)kk * 8u + bKC) ^ xw) * 4u;
            uint32_t af[4][4], bf[4][2];
            #pragma unroll
            for (int mt = 0; mt < 4; mt++)
                ldsm4(af[mt], AsB + aRow[mt] + aOff);
            #pragma unroll
            for (int nt = 0; nt < 4; nt++)
                ldsm2(bf[nt], BsB + bRow[nt] + bOff);
            #pragma unroll
            for (int mt = 0; mt < 4; mt++)
                #pragma unroll
                for (int nt = 0; nt < 4; nt++)
                    mma16(c[mt][nt], af[mt], bf[nt][0], bf[nt][1]);
        }
        mbar_arrive(mb + 24u + 8u * (uint32_t)r);

        if (++r == 3) { r = 0; qd++; }
    }

    // ---------------- epilogue ----------------
    #pragma unroll
    for (int mt = 0; mt < 4; mt++) {
        #pragma unroll
        for (int rr = 0; rr < 2; rr++) {
            const int gm = rowBase + wr * 64 + mt * 16 + ra + rr * 8;
            int wb = 0, n = 0; size_t orow = 0;
            if (MODE == 0) { wb = gm / 49; n = gm - wb * 49; }
            if (MODE == 1) {
                wb = gm / 49; n = gm - wb * 49;
                int b = wb >> 6; int widx = wb & 63;
                int ii = (widx >> 3) * 7 + n / 7;
                int jj = (widx & 7) * 7 + n % 7;
                int oi = ii + 3; if (oi >= 56) oi -= 56;
                int oj = jj + 3; if (oj >= 56) oj -= 56;
                orow = ((size_t)b * 3136 + oi * 56 + oj) * 256;
            }
            if (MODE == 2 || MODE == 3) orow = (size_t)gm * ldo;

            #pragma unroll
            for (int nt = 0; nt < 4; nt++) {
                const int gc = colBase + wc * 32 + nt * 8 + 2 * ca;
                float2 bb = *(const float2*)(bias + gc);
                float v0 = c[mt][nt][rr * 2 + 0] + bb.x;
                float v1 = c[mt][nt][rr * 2 + 1] + bb.y;

                if (MODE == 0) {
                    int part = gc >> 8;
                    int hh = (gc >> 5) & 7;
                    int dd = gc & 31;
                    __nv_bfloat16* Op = (__nv_bfloat16*)((part == 0) ? O0 : ((part == 1) ? O1 : O2));
                    if (part == 0) { v0 *= SCALE; v1 *= SCALE; }
                    *(uint32_t*)(Op + (((size_t)wb * 8 + hh) * 49 + n) * 32 + dd)
                        = bfp(v0, v1);
                } else if (MODE == 1) {
                    float2 rr2 = *(const float2*)(res + orow + gc);
                    *(float2*)(O0 + orow + gc) = make_float2(rr2.x + v0, rr2.y + v1);
                } else if (MODE == 2) {
                    v0 = 0.5f * v0 * (1.0f + erff(v0 * 0.70710678118654752f));
                    v1 = 0.5f * v1 * (1.0f + erff(v1 * 0.70710678118654752f));
                    *(uint32_t*)(Ob + orow + gc) = bfp(v0, v1);
                } else {
                    float2 rr2 = *(const float2*)(res + orow + gc);
                    *(float2*)(O0 + orow + gc) = make_float2(rr2.x + v0, rr2.y + v1);
                }
            }
        }
    }
}

// ----------------------------------------------------------------------------
extern "C" void kernel_launch(void* const* d_in, const int* in_sizes, int n_in,
                              void* d_out, int out_size)
{
    const float* x      = (const float*)d_in[0];
    const float* mask   = (const float*)d_in[1];
    const float* n1g    = (const float*)d_in[2];
    const float* n1b    = (const float*)d_in[3];
    const float* qkv_w  = (const float*)d_in[4];
    const float* qkv_b  = (const float*)d_in[5];
    const float* relb   = (const float*)d_in[6];
    const float* proj_w = (const float*)d_in[7];
    const float* proj_b = (const float*)d_in[8];
    const float* n2g    = (const float*)d_in[9];
    const float* n2b    = (const float*)d_in[10];
    const float* fc1_w  = (const float*)d_in[11];
    const float* fc1_b  = (const float*)d_in[12];
    const float* fc2_w  = (const float*)d_in[13];
    const float* fc2_b  = (const float*)d_in[14];
    float* out = (float*)d_out;

    float *p_x2, *p_btile;
    __nv_bfloat16 *p_q, *p_k, *p_v;
    __nv_bfloat16 *p_hw, *p_o, *p_h2n, *p_mlp;
    __nv_bfloat16 *p_wqkv, *p_wprj, *p_wfc1, *p_wfc2;
    cudaGetSymbolAddress((void**)&p_x2,    g_x2);
    cudaGetSymbolAddress((void**)&p_btile, g_btile);
    cudaGetSymbolAddress((void**)&p_q,     g_q_bf);
    cudaGetSymbolAddress((void**)&p_k,     g_k_bf);
    cudaGetSymbolAddress((void**)&p_v,     g_v_bf);
    cudaGetSymbolAddress((void**)&p_hw,    g_hw_bf);
    cudaGetSymbolAddress((void**)&p_o,     g_o_bf);
    cudaGetSymbolAddress((void**)&p_h2n,   g_h2n_bf);
    cudaGetSymbolAddress((void**)&p_mlp,   g_mlp_bf);
    cudaGetSymbolAddress((void**)&p_wqkv,  g_wqkv_bf);
    cudaGetSymbolAddress((void**)&p_wprj,  g_wprj_bf);
    cudaGetSymbolAddress((void**)&p_wfc1,  g_wfc1_bf);
    cudaGetSymbolAddress((void**)&p_wfc2,  g_wfc2_bf);

    cudaFuncSetAttribute(mma_gemm<0>, cudaFuncAttributeMaxDynamicSharedMemorySize, GEMM_SMEM);
    cudaFuncSetAttribute(mma_gemm<1>, cudaFuncAttributeMaxDynamicSharedMemorySize, GEMM_SMEM);
    cudaFuncSetAttribute(mma_gemm<2>, cudaFuncAttributeMaxDynamicSharedMemorySize, GEMM_SMEM);
    cudaFuncSetAttribute(mma_gemm<3>, cudaFuncAttributeMaxDynamicSharedMemorySize, GEMM_SMEM);

    // 0. fused prep: bias tiles + weight bf16 conversion
    prep_all<<<1280, 256>>>(relb, mask, p_btile,
                            (const float4*)qkv_w, (const float4*)proj_w,
                            (const float4*)fc1_w, (const float4*)fc2_w,
                            (uint2*)p_wqkv, (uint2*)p_wprj,
                            (uint2*)p_wfc1, (uint2*)p_wfc2);
    // 1. LN1 + shift + window partition -> bf16
    ln_kernel<<<TOKENS / 8, 256>>>(x, p_hw, n1g, n1b, 1);
    // 2. QKV (bf16 mma) -> q(scaled)/k/v bf16 in (wb,h,n,d)
    mma_gemm<0><<<dim3(6, 392), 256, GEMM_SMEM>>>(p_hw, p_wqkv, qkv_b, nullptr,
                                                  (float*)p_q, (float*)p_k, (float*)p_v,
                                                  nullptr, 256, 0);
    // 3. Windowed MSA (bf16 tensor-core, ldmatrix + trans for V) -> bf16
    attn_mma<<<8192, 128>>>(p_btile);
    // 4. proj (bf16 mma) + window-reverse + un-roll + residual(x) -> f32
    mma_gemm<1><<<dim3(2, 392), 256, GEMM_SMEM>>>(p_o, p_wprj, proj_b, x,
                                                  p_x2, nullptr, nullptr, nullptr, 256, 256);
    // 5. LN2 -> bf16
    ln_kernel<<<TOKENS / 8, 256>>>(p_x2, p_h2n, n2g, n2b, 0);
    // 6. fc1 (bf16 mma) + GELU -> bf16
    mma_gemm<2><<<dim3(8, 392), 256, GEMM_SMEM>>>(p_h2n, p_wfc1, fc1_b, nullptr,
                                                  nullptr, nullptr, nullptr, p_mlp, 256, 1024);
    // 7. fc2 (bf16 mma) + residual(x2) -> out
    mma_gemm<3><<<dim3(2, 392), 256, GEMM_SMEM>>>(p_mlp, p_wfc2, fc2_b, p_x2,
                                                  out, nullptr, nullptr, nullptr, 1024, 256);
}